// round 9
// baseline (speedup 1.0000x reference)
#include <cuda_runtime.h>
#include <math.h>

#define NN 50000
#define EE 800000
#define HH 128
#define GG 50
#define FF 128
#define BB 256

#define TILE 128          // rows (nodes or edges) per block-tile
#define PAD 132           // smem row stride (multiple of 4 for 16B-aligned loads)
#define NTHREADS 256      // 8 warps; each warp covers 16 rows, lanes cover 128 feats
#define NB_NODE ((NN + TILE - 1) / TILE)   // 391
#define NT_EDGE (EE / TILE)                // 6250
#define EDGE_BLOCKS 148

typedef unsigned long long u64;

// ---------------- scratch (device globals; 16B-aligned for float4 access) -----
__device__ __align__(16) float g_h2[NN * HH];
__device__ __align__(16) float g_xf[NN * FF];
__device__ __align__(16) float g_agg[NN * FF];
__device__ __align__(16) float g_hbuf[NN * HH];
__device__ float g_state2[BB * 2];
__device__ float g_pool[BB];
__device__ float g_cnt[BB];
__device__ int   g_tile_ctr;

// shifted softplus: log(1+e^x) - log(2)
__device__ __forceinline__ float ssp(float x) {
    float sp = (x > 15.0f) ? x : log1pf(__expf(x));
    return sp - 0.69314718055994531f;
}

// ---- packed fp32x2 helpers (Blackwell dual-rate fp32 path) --------------------
__device__ __forceinline__ u64 pk2(float v) {
    u64 r;
    unsigned u = __float_as_uint(v);
    asm("mov.b64 %0, {%1, %1};" : "=l"(r) : "r"(u));
    return r;
}
__device__ __forceinline__ float2 upk(u64 p) {
    unsigned lo, hi;
    asm("mov.b64 {%0, %1}, %2;" : "=r"(lo), "=r"(hi) : "l"(p));
    return make_float2(__uint_as_float(lo), __uint_as_float(hi));
}
#define FMA2(acc, a, b) \
    asm("fma.rn.f32x2 %0, %1, %2, %0;" : "+l"(acc) : "l"(a), "l"(b))

// 16t x 4f register tile, t-pair packed, explicit 1-step prefetch.
// acc[tp*4+fi]: t-pair (t0+2tp, t0+2tp+1), feature f0+fi.
// sW: [k][f] stride 128; sX: [k][t] stride LD.
// NOTE: reads ONE row beyond both sW and sX on the final prefetch — caller must
// guarantee those addresses are within the smem allocation (guard rows/regions).
template <int K, int LD>
__device__ __forceinline__ void gemm16(const float* __restrict__ sW,
                                       const float* __restrict__ sX,
                                       int f0, int t0, u64 acc[32]) {
    const float* xp = sX + t0;
    const float* wp = sW + f0;
    float4 w = *(const float4*)wp;
    ulonglong2 A0 = *(const ulonglong2*)(xp);
    ulonglong2 A1 = *(const ulonglong2*)(xp + 4);
    ulonglong2 A2 = *(const ulonglong2*)(xp + 8);
    ulonglong2 A3 = *(const ulonglong2*)(xp + 12);
#pragma unroll 4
    for (int k = 0; k < K; k++) {
        xp += LD;
        wp += 128;
        float4 wn = *(const float4*)wp;            // prefetch k+1
        ulonglong2 B0 = *(const ulonglong2*)(xp);
        ulonglong2 B1 = *(const ulonglong2*)(xp + 4);
        ulonglong2 B2 = *(const ulonglong2*)(xp + 8);
        ulonglong2 B3 = *(const ulonglong2*)(xp + 12);
        u64 wd0 = pk2(w.x), wd1 = pk2(w.y), wd2 = pk2(w.z), wd3 = pk2(w.w);
        FMA2(acc[0],  A0.x, wd0); FMA2(acc[1],  A0.x, wd1);
        FMA2(acc[2],  A0.x, wd2); FMA2(acc[3],  A0.x, wd3);
        FMA2(acc[4],  A0.y, wd0); FMA2(acc[5],  A0.y, wd1);
        FMA2(acc[6],  A0.y, wd2); FMA2(acc[7],  A0.y, wd3);
        FMA2(acc[8],  A1.x, wd0); FMA2(acc[9],  A1.x, wd1);
        FMA2(acc[10], A1.x, wd2); FMA2(acc[11], A1.x, wd3);
        FMA2(acc[12], A1.y, wd0); FMA2(acc[13], A1.y, wd1);
        FMA2(acc[14], A1.y, wd2); FMA2(acc[15], A1.y, wd3);
        FMA2(acc[16], A2.x, wd0); FMA2(acc[17], A2.x, wd1);
        FMA2(acc[18], A2.x, wd2); FMA2(acc[19], A2.x, wd3);
        FMA2(acc[20], A2.y, wd0); FMA2(acc[21], A2.y, wd1);
        FMA2(acc[22], A2.y, wd2); FMA2(acc[23], A2.y, wd3);
        FMA2(acc[24], A3.x, wd0); FMA2(acc[25], A3.x, wd1);
        FMA2(acc[26], A3.x, wd2); FMA2(acc[27], A3.x, wd3);
        FMA2(acc[28], A3.y, wd0); FMA2(acc[29], A3.y, wd1);
        FMA2(acc[30], A3.y, wd2); FMA2(acc[31], A3.y, wd3);
        w = wn;
        A0 = B0; A1 = B1; A2 = B2; A3 = B3;
    }
}

// ---------------- small helper kernels ----------------------------------------
__global__ void k_init(const float* __restrict__ state_attr) {
    int b = blockIdx.x * blockDim.x + threadIdx.x;
    if (b < BB) {
        g_cnt[b] = 0.0f;
        g_pool[b] = 0.0f;
        g_state2[2 * b]     = state_attr[2 * b];
        g_state2[2 * b + 1] = state_attr[2 * b + 1];
    }
}

__global__ void k_count(const int* __restrict__ batch) {
    int n = blockIdx.x * blockDim.x + threadIdx.x;
    if (n < NN) atomicAdd(&g_cnt[batch[n]], 1.0f);
}

__global__ void k_state() {
    int b = threadIdx.x;
    if (b < BB) {
        float s = g_pool[b] / fmaxf(g_cnt[b], 1.0f);
        g_state2[2 * b]     = s;
        g_state2[2 * b + 1] = s;
        g_pool[b] = 0.0f;
    }
}

__global__ void k_reset() {
    if (threadIdx.x == 0) g_tile_ctr = 0;
}

// ---------------- node GEMM kernel (4 modes) -----------------------------------
// MODE 0: h2 = [sa,h] @ lin1_w^T + b   (X = h input), writes g_h2, zeroes g_agg
// MODE 1: xf = g_h2 @ conv_lin1_w^T,   writes g_xf
// MODE 2: h  = g_h2 + ssp(g_agg @ conv_lin2_w^T + b), writes g_hbuf (+pool)
// MODE 3: out = g_hbuf @ out_w^T + b,  writes Yext (d_out)
// layout: sW [0,16384) -> sb(128) sw0(128) sw1(128) spool(128) ssa0(128) ssa1(128)
//         sX at 17152, region 128*PAD + guard row PAD
#define NODE_SMEM_FLOATS (17152 + (TILE + 1) * PAD)
#define NODE_SMEM_BYTES  (NODE_SMEM_FLOATS * 4)

template <int MODE>
__global__ void __launch_bounds__(NTHREADS, 1)
node_gemm(const float* __restrict__ Xext, const float* __restrict__ W,
          const float* __restrict__ bias, const int* __restrict__ batch,
          float* __restrict__ Yext, int do_pool) {
    extern __shared__ float sm[];
    float* sW    = sm;            // 16384
    float* sb    = sm + 16384;    // 128 (also absorbs sW prefetch overrun)
    float* sw0   = sm + 16512;    // 128
    float* sw1   = sm + 16640;    // 128
    float* spool = sm + 16768;    // 128
    float* ssa0  = sm + 16896;    // 128
    float* ssa1  = sm + 17024;    // 128
    float* sX    = sm + 17152;    // 128*PAD + guard row

    const int tid = threadIdx.x;
    const int n0  = blockIdx.x * TILE;

    const float* X;
    float* Y;
    float* aux = 0;
    if (MODE == 0)      { X = Xext ? Xext : g_hbuf; Y = g_h2;   aux = g_agg; }
    else if (MODE == 1) { X = g_h2;                 Y = g_xf; }
    else if (MODE == 2) { X = g_agg;                Y = g_hbuf; aux = g_h2; }
    else                { X = g_hbuf;               Y = Yext; }

    constexpr int ldw  = (MODE == 0) ? 130 : 128;
    constexpr int woff = (MODE == 0) ? 2 : 0;

    for (int i = tid; i < 128 * 128; i += NTHREADS) {
        int f = i >> 7, k = i & 127;
        sW[k * 128 + f] = W[f * ldw + woff + k];
    }
    if (tid < 128) {
        sb[tid] = bias ? bias[tid] : 0.0f;
        spool[tid] = 0.0f;
        if (MODE == 0) {
            sw0[tid] = W[tid * 130];
            sw1[tid] = W[tid * 130 + 1];
            float a0 = 0.0f, a1 = 0.0f;
            int n = n0 + tid;
            if (n < NN) {
                int b = batch[n];
                a0 = g_state2[2 * b];
                a1 = g_state2[2 * b + 1];
            }
            ssa0[tid] = a0;
            ssa1[tid] = a1;
        }
    }
    for (int i = tid; i < TILE * 128; i += NTHREADS) {
        int t = i >> 7, k = i & 127;
        int n = n0 + t;
        sX[k * PAD + t] = (n < NN) ? X[(size_t)n * 128 + k] : 0.0f;
    }
    __syncthreads();

    const int f0 = (tid & 31) * 4;
    const int t0 = (tid >> 5) * 16;

    u64 acc[32];
    if (MODE == 1) {
#pragma unroll
        for (int i = 0; i < 32; i++) acc[i] = 0ull;
    } else {
#pragma unroll
        for (int fi = 0; fi < 4; fi++) {
            u64 bp = pk2(sb[f0 + fi]);
#pragma unroll
            for (int tp = 0; tp < 8; tp++) acc[tp * 4 + fi] = bp;
        }
    }

    if (MODE == 0) {
        ulonglong2 Sa = *(const ulonglong2*)&ssa0[t0];
        ulonglong2 Sb = *(const ulonglong2*)&ssa0[t0 + 4];
        ulonglong2 Sc = *(const ulonglong2*)&ssa0[t0 + 8];
        ulonglong2 Sd = *(const ulonglong2*)&ssa0[t0 + 12];
        ulonglong2 Ta = *(const ulonglong2*)&ssa1[t0];
        ulonglong2 Tb = *(const ulonglong2*)&ssa1[t0 + 4];
        ulonglong2 Tc = *(const ulonglong2*)&ssa1[t0 + 8];
        ulonglong2 Td = *(const ulonglong2*)&ssa1[t0 + 12];
        u64 sp[8] = {Sa.x, Sa.y, Sb.x, Sb.y, Sc.x, Sc.y, Sd.x, Sd.y};
        u64 tq[8] = {Ta.x, Ta.y, Tb.x, Tb.y, Tc.x, Tc.y, Td.x, Td.y};
#pragma unroll
        for (int fi = 0; fi < 4; fi++) {
            u64 w0d = pk2(sw0[f0 + fi]);
            u64 w1d = pk2(sw1[f0 + fi]);
#pragma unroll
            for (int tp = 0; tp < 8; tp++) {
                FMA2(acc[tp * 4 + fi], sp[tp], w0d);
                FMA2(acc[tp * 4 + fi], tq[tp], w1d);
            }
        }
    }

    gemm16<128, PAD>(sW, sX, f0, t0, acc);

#pragma unroll
    for (int tp = 0; tp < 8; tp++) {
        float2 p0 = upk(acc[tp * 4 + 0]);
        float2 p1 = upk(acc[tp * 4 + 1]);
        float2 p2 = upk(acc[tp * 4 + 2]);
        float2 p3 = upk(acc[tp * 4 + 3]);
        float4 v[2];
        v[0] = make_float4(p0.x, p1.x, p2.x, p3.x);
        v[1] = make_float4(p0.y, p1.y, p2.y, p3.y);
#pragma unroll
        for (int hh = 0; hh < 2; hh++) {
            int t = t0 + 2 * tp + hh;
            int n = n0 + t;
            if (n >= NN) continue;
            size_t off = (size_t)n * 128 + f0;
            if (MODE == 0) {
                *(float4*)&Y[off]   = v[hh];
                *(float4*)&aux[off] = make_float4(0.f, 0.f, 0.f, 0.f);
            } else if (MODE == 2) {
                float4 h2v = *(const float4*)&aux[off];
                float4 o;
                o.x = h2v.x + ssp(v[hh].x);
                o.y = h2v.y + ssp(v[hh].y);
                o.z = h2v.z + ssp(v[hh].z);
                o.w = h2v.w + ssp(v[hh].w);
                *(float4*)&Y[off] = o;
                if (do_pool) atomicAdd(&spool[t], o.x + o.y + o.z + o.w);
            } else {
                *(float4*)&Y[off] = v[hh];
            }
        }
    }

    if (MODE == 2 && do_pool) {
        __syncthreads();
        if (tid < TILE) {
            int n = n0 + tid;
            if (n < NN) atomicAdd(&g_pool[batch[n]], spool[tid]);
        }
    }
}

// ---------------- fused edge kernel --------------------------------------------
// Per 128-edge tile: z = ssp(ea @ W1^T + b1); eh = z @ W2^T + b2;
// msg = eh * C * xf[src]; vector-red into agg[dst]. Persistent + work stealing.
// layout: sW1[0,6400) sb1(128, absorbs sW1 overrun) sW2[6528,22912) sb2(128)
//         sC(128) sSrc(128) sDst(128) sEA@23424 (50*PAD; overrun lands in sZ)
//         sZ@30024 (128*PAD + guard row)
#define EDGE_SMEM_FLOATS (30024 + (TILE + 1) * PAD)
#define EDGE_SMEM_BYTES  (EDGE_SMEM_FLOATS * 4)

__global__ void __launch_bounds__(NTHREADS, 1)
edge_kernel(const float* __restrict__ ea, const float* __restrict__ ew,
            const int* __restrict__ eidx,
            const float* __restrict__ W1, const float* __restrict__ b1,
            const float* __restrict__ W2, const float* __restrict__ b2) {
    extern __shared__ float sm[];
    float* sW1 = sm;                   // 50*128 = 6400
    float* sb1 = sm + 6400;            // 128
    float* sW2 = sm + 6528;            // 16384
    float* sb2 = sm + 22912;           // 128
    float* sC  = sm + 23040;           // 128
    int* sSrc  = (int*)(sm + 23168);   // 128
    int* sDst  = (int*)(sm + 23296);   // 128
    float* sEA = sm + 23424;           // 50*PAD = 6600
    float* sZ  = sm + 30024;           // 128*PAD + guard row
    __shared__ int s_tile;

    const int tid = threadIdx.x;

    for (int i = tid; i < 128 * 50; i += NTHREADS) {
        int f = i / 50, k = i - f * 50;
        sW1[k * 128 + f] = W1[i];
    }
    for (int i = tid; i < 128 * 128; i += NTHREADS) {
        int f = i >> 7, k = i & 127;
        sW2[k * 128 + f] = W2[i];
    }
    if (tid < 128) {
        sb1[tid] = b1[tid];
        sb2[tid] = b2[tid];
    }

    const int f0 = (tid & 31) * 4;
    const int t0 = (tid >> 5) * 16;

    for (;;) {
        __syncthreads();
        if (tid == 0) s_tile = atomicAdd(&g_tile_ctr, 1);
        __syncthreads();
        const int tile = s_tile;
        if (tile >= NT_EDGE) break;
        const int e0 = tile * TILE;

        for (int i = tid; i < TILE * 50; i += NTHREADS) {
            int t = i / 50, k = i - t * 50;
            sEA[k * PAD + t] = ea[(size_t)(e0 + t) * 50 + k];
        }
        if (tid < TILE) {
            int e = e0 + tid;
            sC[tid]  = 0.5f * (__cosf(ew[e] * 0.62831853071795864769f) + 1.0f);
            sSrc[tid] = eidx[e];
            sDst[tid] = eidx[EE + e];
        }
        __syncthreads();

        // stage 1: z = ssp(ea @ W1^T + b1), stored [k][t]
        {
            u64 acc[32];
#pragma unroll
            for (int fi = 0; fi < 4; fi++) {
                u64 bp = pk2(sb1[f0 + fi]);
#pragma unroll
                for (int tp = 0; tp < 8; tp++) acc[tp * 4 + fi] = bp;
            }
            gemm16<50, PAD>(sW1, sEA, f0, t0, acc);
#pragma unroll
            for (int fi = 0; fi < 4; fi++) {
#pragma unroll
                for (int tp = 0; tp < 8; tp += 2) {
                    float2 pa = upk(acc[tp * 4 + fi]);
                    float2 pb = upk(acc[(tp + 1) * 4 + fi]);
                    float4 o;
                    o.x = ssp(pa.x);
                    o.y = ssp(pa.y);
                    o.z = ssp(pb.x);
                    o.w = ssp(pb.y);
                    *(float4*)&sZ[(f0 + fi) * PAD + t0 + 2 * tp] = o;
                }
            }
        }
        __syncthreads();

        // stage 2: eh = z @ W2^T + b2; msg = eh*C*xf[src]; vector-red to agg[dst]
        {
            u64 acc[32];
#pragma unroll
            for (int fi = 0; fi < 4; fi++) {
                u64 bp = pk2(sb2[f0 + fi]);
#pragma unroll
                for (int tp = 0; tp < 8; tp++) acc[tp * 4 + fi] = bp;
            }
            gemm16<128, PAD>(sW2, sZ, f0, t0, acc);
#pragma unroll
            for (int tp = 0; tp < 8; tp++) {
                float2 p0 = upk(acc[tp * 4 + 0]);
                float2 p1 = upk(acc[tp * 4 + 1]);
                float2 p2 = upk(acc[tp * 4 + 2]);
                float2 p3 = upk(acc[tp * 4 + 3]);
                float4 v[2];
                v[0] = make_float4(p0.x, p1.x, p2.x, p3.x);
                v[1] = make_float4(p0.y, p1.y, p2.y, p3.y);
#pragma unroll
                for (int hh = 0; hh < 2; hh++) {
                    int t = t0 + 2 * tp + hh;
                    float c = sC[t];
                    int s = sSrc[t], d = sDst[t];
                    float4 x4 = *(const float4*)&g_xf[(size_t)s * 128 + f0];
                    float4 m;
                    m.x = v[hh].x * c * x4.x;
                    m.y = v[hh].y * c * x4.y;
                    m.z = v[hh].z * c * x4.z;
                    m.w = v[hh].w * c * x4.w;
                    float* ap = g_agg + (size_t)d * 128 + f0;
                    asm volatile("red.global.add.v4.f32 [%0], {%1, %2, %3, %4};"
                                 :: "l"(ap), "f"(m.x), "f"(m.y), "f"(m.z), "f"(m.w)
                                 : "memory");
                }
            }
        }
    }
}

// ---------------- launcher -----------------------------------------------------
extern "C" void kernel_launch(void* const* d_in, const int* in_sizes, int n_in,
                              void* d_out, int out_size) {
    const float* h      = (const float*)d_in[0];
    const float* ew     = (const float*)d_in[1];
    const float* ea     = (const float*)d_in[2];
    const float* st     = (const float*)d_in[3];
    const float* lin1w  = (const float*)d_in[4];
    const float* lin1b  = (const float*)d_in[5];
    const float* mw1    = (const float*)d_in[6];
    const float* mb1    = (const float*)d_in[7];
    const float* mw2    = (const float*)d_in[8];
    const float* mb2    = (const float*)d_in[9];
    const float* cl1    = (const float*)d_in[10];
    const float* cl2    = (const float*)d_in[11];
    const float* cl2b   = (const float*)d_in[12];
    const float* outw   = (const float*)d_in[13];
    const float* outb   = (const float*)d_in[14];
    const int* eidx  = (const int*)d_in[15];
    const int* batch = (const int*)d_in[16];
    float* out = (float*)d_out;

    cudaFuncSetAttribute(node_gemm<0>, cudaFuncAttributeMaxDynamicSharedMemorySize, NODE_SMEM_BYTES);
    cudaFuncSetAttribute(node_gemm<1>, cudaFuncAttributeMaxDynamicSharedMemorySize, NODE_SMEM_BYTES);
    cudaFuncSetAttribute(node_gemm<2>, cudaFuncAttributeMaxDynamicSharedMemorySize, NODE_SMEM_BYTES);
    cudaFuncSetAttribute(node_gemm<3>, cudaFuncAttributeMaxDynamicSharedMemorySize, NODE_SMEM_BYTES);
    cudaFuncSetAttribute(edge_kernel,  cudaFuncAttributeMaxDynamicSharedMemorySize, EDGE_SMEM_BYTES);

    k_init<<<1, 256>>>(st);
    k_count<<<(NN + 255) / 256, 256>>>(batch);

    for (int i = 0; i < 2; i++) {
        const float* hin = (i == 0) ? h : (const float*)0;  // null => g_hbuf
        node_gemm<0><<<NB_NODE, NTHREADS, NODE_SMEM_BYTES>>>(
            hin, lin1w + i * 128 * 130, lin1b + i * 128, batch, (float*)0, 0);
        node_gemm<1><<<NB_NODE, NTHREADS, NODE_SMEM_BYTES>>>(
            (const float*)0, cl1 + i * 128 * 128, (const float*)0, batch, (float*)0, 0);
        k_reset<<<1, 32>>>();
        edge_kernel<<<EDGE_BLOCKS, NTHREADS, EDGE_SMEM_BYTES>>>(
            ea, ew, eidx, mw1 + i * 128 * 50, mb1 + i * 128,
            mw2 + i * 128 * 128, mb2 + i * 128);
        node_gemm<2><<<NB_NODE, NTHREADS, NODE_SMEM_BYTES>>>(
            (const float*)0, cl2 + i * 128 * 128, cl2b + i * 128, batch, (float*)0,
            (i == 0) ? 1 : 0);
        if (i == 0) k_state<<<1, 256>>>();
    }
    node_gemm<3><<<NB_NODE, NTHREADS, NODE_SMEM_BYTES>>>(
        (const float*)0, outw, outb, batch, out, 0);
}

// round 11
// speedup vs baseline: 1.3265x; 1.3265x over previous
#include <cuda_runtime.h>
#include <math.h>

#define NN 50000
#define EE 800000
#define HH 128
#define GG 50
#define FF 128
#define BB 256

#define TILE 128
#define PAD 132
#define NTHREADS 512
#define NB_NODE ((NN + TILE - 1) / TILE)   // 391
#define NT_EDGE (EE / TILE)                // 6250
#define EDGE_BLOCKS 148
#define ETHREADS 256                       // edge kernel: 8 warps

typedef unsigned long long u64;

// ---------------- scratch -------------------------------------------------------
__device__ __align__(16) float g_h2[NN * HH];
__device__ __align__(16) float g_xf[NN * FF];
__device__ __align__(16) float g_agg[NN * FF];
__device__ __align__(16) float g_hbuf[NN * HH];
__device__ float g_state2[BB * 2];
__device__ float g_pool[BB];
__device__ float g_cnt[BB];
__device__ int   g_tile_ctr;

__device__ __forceinline__ float ssp(float x) {
    float sp = (x > 15.0f) ? x : log1pf(__expf(x));
    return sp - 0.69314718055994531f;
}

// ---- packed fp32x2 helpers (node GEMMs) ---------------------------------------
__device__ __forceinline__ u64 pk2(float v) {
    u64 r;
    unsigned u = __float_as_uint(v);
    asm("mov.b64 %0, {%1, %1};" : "=l"(r) : "r"(u));
    return r;
}
__device__ __forceinline__ float2 upk(u64 p) {
    unsigned lo, hi;
    asm("mov.b64 {%0, %1}, %2;" : "=r"(lo), "=r"(hi) : "l"(p));
    return make_float2(__uint_as_float(lo), __uint_as_float(hi));
}
#define FMA2(acc, a, b) \
    asm("fma.rn.f32x2 %0, %1, %2, %0;" : "+l"(acc) : "l"(a), "l"(b))

template <int K, int LD>
__device__ __forceinline__ void gemm_tile_p(const float* __restrict__ sW,
                                            const float* __restrict__ sX,
                                            int f0, int t0, u64 acc[16]) {
    const float* xp = sX + t0;
    const float* wp = sW + f0;
#pragma unroll 4
    for (int k = 0; k < K; k++) {
        float4 w4 = *(const float4*)wp;
        ulonglong2 A0 = *(const ulonglong2*)xp;
        ulonglong2 A1 = *(const ulonglong2*)(xp + 4);
        u64 wd0 = pk2(w4.x), wd1 = pk2(w4.y), wd2 = pk2(w4.z), wd3 = pk2(w4.w);
        FMA2(acc[0],  A0.x, wd0); FMA2(acc[1],  A0.x, wd1);
        FMA2(acc[2],  A0.x, wd2); FMA2(acc[3],  A0.x, wd3);
        FMA2(acc[4],  A0.y, wd0); FMA2(acc[5],  A0.y, wd1);
        FMA2(acc[6],  A0.y, wd2); FMA2(acc[7],  A0.y, wd3);
        FMA2(acc[8],  A1.x, wd0); FMA2(acc[9],  A1.x, wd1);
        FMA2(acc[10], A1.x, wd2); FMA2(acc[11], A1.x, wd3);
        FMA2(acc[12], A1.y, wd0); FMA2(acc[13], A1.y, wd1);
        FMA2(acc[14], A1.y, wd2); FMA2(acc[15], A1.y, wd3);
        xp += LD;
        wp += 128;
    }
}

// ---- tf32 mma helpers ----------------------------------------------------------
__device__ __forceinline__ float f2tf(float x) {   // round-to-nearest tf32
    unsigned r;
    asm("cvt.rna.tf32.f32 %0, %1;" : "=r"(r) : "f"(x));
    return __uint_as_float(r);
}
#define MMA_TF32(c, a, b) \
    asm volatile("mma.sync.aligned.m16n8k8.row.col.f32.tf32.tf32.f32 " \
        "{%0,%1,%2,%3}, {%4,%5,%6,%7}, {%8,%9}, {%0,%1,%2,%3};" \
        : "+f"((c)[0]), "+f"((c)[1]), "+f"((c)[2]), "+f"((c)[3]) \
        : "r"((a)[0]), "r"((a)[1]), "r"((a)[2]), "r"((a)[3]), \
          "r"((b)[0]), "r"((b)[1]))

// ---------------- small helper kernels -----------------------------------------
__global__ void k_init(const float* __restrict__ state_attr) {
    int b = blockIdx.x * blockDim.x + threadIdx.x;
    if (b < BB) {
        g_cnt[b] = 0.0f;
        g_pool[b] = 0.0f;
        g_state2[2 * b]     = state_attr[2 * b];
        g_state2[2 * b + 1] = state_attr[2 * b + 1];
    }
}
__global__ void k_count(const int* __restrict__ batch) {
    int n = blockIdx.x * blockDim.x + threadIdx.x;
    if (n < NN) atomicAdd(&g_cnt[batch[n]], 1.0f);
}
__global__ void k_state() {
    int b = threadIdx.x;
    if (b < BB) {
        float s = g_pool[b] / fmaxf(g_cnt[b], 1.0f);
        g_state2[2 * b]     = s;
        g_state2[2 * b + 1] = s;
        g_pool[b] = 0.0f;
    }
}
__global__ void k_reset() {
    if (threadIdx.x == 0) g_tile_ctr = 0;
}

// ---------------- node GEMM kernel (R7 config, unchanged) ----------------------
#define NODE_SMEM_FLOATS (17152 + TILE * PAD)
#define NODE_SMEM_BYTES  (NODE_SMEM_FLOATS * 4)

template <int MODE>
__global__ void __launch_bounds__(NTHREADS, 1)
node_gemm(const float* __restrict__ Xext, const float* __restrict__ W,
          const float* __restrict__ bias, const int* __restrict__ batch,
          float* __restrict__ Yext, int do_pool) {
    extern __shared__ float sm[];
    float* sW    = sm;
    float* sb    = sm + 16384;
    float* sw0   = sm + 16512;
    float* sw1   = sm + 16640;
    float* spool = sm + 16768;
    float* ssa0  = sm + 16896;
    float* ssa1  = sm + 17024;
    float* sX    = sm + 17152;

    const int tid = threadIdx.x;
    const int n0  = blockIdx.x * TILE;

    const float* X;
    float* Y;
    float* aux = 0;
    if (MODE == 0)      { X = Xext ? Xext : g_hbuf; Y = g_h2;   aux = g_agg; }
    else if (MODE == 1) { X = g_h2;                 Y = g_xf; }
    else if (MODE == 2) { X = g_agg;                Y = g_hbuf; aux = g_h2; }
    else                { X = g_hbuf;               Y = Yext; }

    constexpr int ldw  = (MODE == 0) ? 130 : 128;
    constexpr int woff = (MODE == 0) ? 2 : 0;

    for (int i = tid; i < 128 * 128; i += NTHREADS) {
        int f = i >> 7, k = i & 127;
        sW[k * 128 + f] = W[f * ldw + woff + k];
    }
    if (tid < 128) {
        sb[tid] = bias ? bias[tid] : 0.0f;
        spool[tid] = 0.0f;
        if (MODE == 0) {
            sw0[tid] = W[tid * 130];
            sw1[tid] = W[tid * 130 + 1];
            float a0 = 0.0f, a1 = 0.0f;
            int n = n0 + tid;
            if (n < NN) {
                int b = batch[n];
                a0 = g_state2[2 * b];
                a1 = g_state2[2 * b + 1];
            }
            ssa0[tid] = a0;
            ssa1[tid] = a1;
        }
    }
    for (int i = tid; i < TILE * 128; i += NTHREADS) {
        int t = i >> 7, k = i & 127;
        int n = n0 + t;
        sX[k * PAD + t] = (n < NN) ? X[(size_t)n * 128 + k] : 0.0f;
    }
    __syncthreads();

    const int f0 = (tid & 31) * 4;
    const int t0 = (tid >> 5) * 8;

    u64 acc[16];
    if (MODE == 1) {
#pragma unroll
        for (int i = 0; i < 16; i++) acc[i] = 0ull;
    } else {
#pragma unroll
        for (int fi = 0; fi < 4; fi++) {
            u64 bp = pk2(sb[f0 + fi]);
            acc[0 * 4 + fi] = bp;
            acc[1 * 4 + fi] = bp;
            acc[2 * 4 + fi] = bp;
            acc[3 * 4 + fi] = bp;
        }
    }

    if (MODE == 0) {
        ulonglong2 Sa = *(const ulonglong2*)&ssa0[t0];
        ulonglong2 Sb = *(const ulonglong2*)&ssa0[t0 + 4];
        ulonglong2 Ta = *(const ulonglong2*)&ssa1[t0];
        ulonglong2 Tb = *(const ulonglong2*)&ssa1[t0 + 4];
#pragma unroll
        for (int fi = 0; fi < 4; fi++) {
            u64 w0d = pk2(sw0[f0 + fi]);
            u64 w1d = pk2(sw1[f0 + fi]);
            FMA2(acc[0 * 4 + fi], Sa.x, w0d);
            FMA2(acc[1 * 4 + fi], Sa.y, w0d);
            FMA2(acc[2 * 4 + fi], Sb.x, w0d);
            FMA2(acc[3 * 4 + fi], Sb.y, w0d);
            FMA2(acc[0 * 4 + fi], Ta.x, w1d);
            FMA2(acc[1 * 4 + fi], Ta.y, w1d);
            FMA2(acc[2 * 4 + fi], Tb.x, w1d);
            FMA2(acc[3 * 4 + fi], Tb.y, w1d);
        }
    }

    gemm_tile_p<128, PAD>(sW, sX, f0, t0, acc);

#pragma unroll
    for (int tp = 0; tp < 4; tp++) {
        float2 p0 = upk(acc[tp * 4 + 0]);
        float2 p1 = upk(acc[tp * 4 + 1]);
        float2 p2 = upk(acc[tp * 4 + 2]);
        float2 p3 = upk(acc[tp * 4 + 3]);
        float4 v[2];
        v[0] = make_float4(p0.x, p1.x, p2.x, p3.x);
        v[1] = make_float4(p0.y, p1.y, p2.y, p3.y);
#pragma unroll
        for (int hh = 0; hh < 2; hh++) {
            int t = t0 + 2 * tp + hh;
            int n = n0 + t;
            if (n >= NN) continue;
            size_t off = (size_t)n * 128 + f0;
            if (MODE == 0) {
                *(float4*)&Y[off]   = v[hh];
                *(float4*)&aux[off] = make_float4(0.f, 0.f, 0.f, 0.f);
            } else if (MODE == 2) {
                float4 h2v = *(const float4*)&aux[off];
                float4 o;
                o.x = h2v.x + ssp(v[hh].x);
                o.y = h2v.y + ssp(v[hh].y);
                o.z = h2v.z + ssp(v[hh].z);
                o.w = h2v.w + ssp(v[hh].w);
                *(float4*)&Y[off] = o;
                if (do_pool) atomicAdd(&spool[t], o.x + o.y + o.z + o.w);
            } else {
                *(float4*)&Y[off] = v[hh];
            }
        }
    }

    if (MODE == 2 && do_pool) {
        __syncthreads();
        if (tid < TILE) {
            int n = n0 + tid;
            if (n < NN) atomicAdd(&g_pool[batch[n]], spool[tid]);
        }
    }
}

// ---------------- fused edge kernel: mma.sync tf32 -----------------------------
// 8 warps. Warp tile 32e x 64f (2 m-strips x 8 n-blocks of m16n8k8).
// stage1: D1 = ea(128x56) @ W1^T -> z = ssp(D1+b1) (tf32) in smem
// stage2: D2 = z(128x128) @ W2^T -> out = D2+b2 staged in smem
// epilogue: msg = out * C * xf[src] -> red.v4 into agg[dst]
// smem float offsets:
#define SEA  0        // ea tile [e][k] stride 60      (7680)
#define SW1P 7680     // W1 packed B-frags kc7 x nb16  (7168)
#define SZ   14848    // z [e][f] stride 132, reused as out (16896)
#define SW2P 31744    // W2 packed B-frags kc16 x nb16 (16384)
#define SB1V 48128
#define SB2V 48256
#define SCV  48384
#define SSRC 48512
#define SDST 48640
#define EDGE_SMEM_BYTES (48768 * 4)

__global__ void __launch_bounds__(ETHREADS, 1)
edge_kernel(const float* __restrict__ ea, const float* __restrict__ ew,
            const int* __restrict__ eidx,
            const float* __restrict__ W1, const float* __restrict__ b1,
            const float* __restrict__ W2, const float* __restrict__ b2) {
    extern __shared__ float sm[];
    int* sSrc = (int*)(sm + SSRC);
    int* sDst = (int*)(sm + SDST);
    __shared__ int s_tile;

    const int tid  = threadIdx.x;
    const int wid  = tid >> 5;
    const int lane = tid & 31;
    const int g    = lane >> 2;     // groupID
    const int tg   = lane & 3;      // threadID_in_group
    const int mq   = wid >> 1;      // m-quad 0..3 -> rows mq*32
    const int nh   = wid & 1;       // n-half 0..1 -> cols nh*64

    // pack W1 (B frags, K padded 50->56), W2; biases
    for (int i = tid; i < 128 * 56; i += ETHREADS) {
        int f = i / 56, k = i - f * 56;
        float v = (k < GG) ? W1[f * GG + k] : 0.0f;
        int idx = (((k >> 3) * 16 + (f >> 3)) * 32 + (f & 7) * 4 + (k & 3)) * 2 + ((k & 7) >> 2);
        sm[SW1P + idx] = f2tf(v);
    }
    for (int i = tid; i < 128 * 128; i += ETHREADS) {
        int f = i >> 7, k = i & 127;
        int idx = (((k >> 3) * 16 + (f >> 3)) * 32 + (f & 7) * 4 + (k & 3)) * 2 + ((k & 7) >> 2);
        sm[SW2P + idx] = f2tf(W2[i]);
    }
    if (tid < 128) {
        sm[SB1V + tid] = b1[tid];
        sm[SB2V + tid] = b2[tid];
    }

    const int rb0 = mq * 32;

    for (;;) {
        __syncthreads();
        if (tid == 0) s_tile = atomicAdd(&g_tile_ctr, 1);
        __syncthreads();
        const int tile = s_tile;
        if (tile >= NT_EDGE) break;
        const int e0 = tile * TILE;

        for (int i = tid; i < 128 * 56; i += ETHREADS) {
            int e = i / 56, k = i - e * 56;
            float v = (k < GG) ? ea[(size_t)(e0 + e) * GG + k] : 0.0f;
            sm[SEA + e * 60 + k] = f2tf(v);
        }
        if (tid < 128) {
            int e = e0 + tid;
            sm[SCV + tid] = 0.5f * (__cosf(ew[e] * 0.62831853071795864769f) + 1.0f);
            sSrc[tid] = eidx[e];
            sDst[tid] = eidx[EE + e];
        }
        __syncthreads();

        float acc[2][8][4];
#pragma unroll
        for (int ms = 0; ms < 2; ms++)
#pragma unroll
            for (int nb = 0; nb < 8; nb++)
#pragma unroll
                for (int q = 0; q < 4; q++) acc[ms][nb][q] = 0.0f;

        // ---- stage 1: K=56 -> 7 chunks
#pragma unroll
        for (int kc = 0; kc < 7; kc++) {
            unsigned a[2][4];
#pragma unroll
            for (int ms = 0; ms < 2; ms++) {
                const float* p = sm + SEA + (rb0 + ms * 16 + g) * 60 + kc * 8 + tg;
                a[ms][0] = __float_as_uint(p[0]);
                a[ms][1] = __float_as_uint(p[8 * 60]);
                a[ms][2] = __float_as_uint(p[4]);
                a[ms][3] = __float_as_uint(p[8 * 60 + 4]);
            }
            unsigned b[8][2];
#pragma unroll
            for (int nb = 0; nb < 8; nb++) {
                float2 bb = *(const float2*)&sm[SW1P + ((kc * 16 + nh * 8 + nb) * 32 + lane) * 2];
                b[nb][0] = __float_as_uint(bb.x);
                b[nb][1] = __float_as_uint(bb.y);
            }
#pragma unroll
            for (int ms = 0; ms < 2; ms++)
#pragma unroll
                for (int nb = 0; nb < 8; nb++)
                    MMA_TF32(acc[ms][nb], a[ms], b[nb]);
        }

        // write z = f2tf(ssp(acc + b1))  [e][f] stride 132
#pragma unroll
        for (int ms = 0; ms < 2; ms++) {
            int r = rb0 + ms * 16 + g;
#pragma unroll
            for (int nb = 0; nb < 8; nb++) {
                int col = nh * 64 + nb * 8 + 2 * tg;
                float bv0 = sm[SB1V + col], bv1 = sm[SB1V + col + 1];
                float2 lo, hi;
                lo.x = f2tf(ssp(acc[ms][nb][0] + bv0));
                lo.y = f2tf(ssp(acc[ms][nb][1] + bv1));
                hi.x = f2tf(ssp(acc[ms][nb][2] + bv0));
                hi.y = f2tf(ssp(acc[ms][nb][3] + bv1));
                *(float2*)&sm[SZ + r * 132 + col]       = lo;
                *(float2*)&sm[SZ + (r + 8) * 132 + col] = hi;
            }
        }
        __syncthreads();

        // ---- stage 2: K=128 -> 16 chunks
#pragma unroll
        for (int ms = 0; ms < 2; ms++)
#pragma unroll
            for (int nb = 0; nb < 8; nb++)
#pragma unroll
                for (int q = 0; q < 4; q++) acc[ms][nb][q] = 0.0f;

#pragma unroll 4
        for (int kc = 0; kc < 16; kc++) {
            unsigned a[2][4];
#pragma unroll
            for (int ms = 0; ms < 2; ms++) {
                const float* p = sm + SZ + (rb0 + ms * 16 + g) * 132 + kc * 8 + tg;
                a[ms][0] = __float_as_uint(p[0]);
                a[ms][1] = __float_as_uint(p[8 * 132]);
                a[ms][2] = __float_as_uint(p[4]);
                a[ms][3] = __float_as_uint(p[8 * 132 + 4]);
            }
            unsigned b[8][2];
#pragma unroll
            for (int nb = 0; nb < 8; nb++) {
                float2 bb = *(const float2*)&sm[SW2P + ((kc * 16 + nh * 8 + nb) * 32 + lane) * 2];
                b[nb][0] = __float_as_uint(bb.x);
                b[nb][1] = __float_as_uint(bb.y);
            }
#pragma unroll
            for (int ms = 0; ms < 2; ms++)
#pragma unroll
                for (int nb = 0; nb < 8; nb++)
                    MMA_TF32(acc[ms][nb], a[ms], b[nb]);
        }
        __syncthreads();   // all reads of sZ complete before overwrite

        // stage out = acc + b2 into sZ
#pragma unroll
        for (int ms = 0; ms < 2; ms++) {
            int r = rb0 + ms * 16 + g;
#pragma unroll
            for (int nb = 0; nb < 8; nb++) {
                int col = nh * 64 + nb * 8 + 2 * tg;
                float bv0 = sm[SB2V + col], bv1 = sm[SB2V + col + 1];
                float2 lo, hi;
                lo.x = acc[ms][nb][0] + bv0;
                lo.y = acc[ms][nb][1] + bv1;
                hi.x = acc[ms][nb][2] + bv0;
                hi.y = acc[ms][nb][3] + bv1;
                *(float2*)&sm[SZ + r * 132 + col]       = lo;
                *(float2*)&sm[SZ + (r + 8) * 132 + col] = hi;
            }
        }
        __syncthreads();

        // epilogue: 2 threads per edge, 64 feats each
        {
            int e  = tid >> 1;
            int fb = (tid & 1) * 64;
            float cenv = sm[SCV + e];
            int s = sSrc[e], d = sDst[e];
            const float* zr = sm + SZ + e * 132 + fb;
            const float* xb = &g_xf[(size_t)s * 128 + fb];
            float* ab = &g_agg[(size_t)d * 128 + fb];
#pragma unroll
            for (int q = 0; q < 16; q++) {
                float4 v = *(const float4*)(zr + 4 * q);
                float4 x = *(const float4*)(xb + 4 * q);
                float mx = v.x * cenv * x.x;
                float my = v.y * cenv * x.y;
                float mz = v.z * cenv * x.z;
                float mw = v.w * cenv * x.w;
                asm volatile("red.global.add.v4.f32 [%0], {%1, %2, %3, %4};"
                             :: "l"(ab + 4 * q), "f"(mx), "f"(my), "f"(mz), "f"(mw)
                             : "memory");
            }
        }
    }
}

// ---------------- launcher -----------------------------------------------------
extern "C" void kernel_launch(void* const* d_in, const int* in_sizes, int n_in,
                              void* d_out, int out_size) {
    const float* h      = (const float*)d_in[0];
    const float* ew     = (const float*)d_in[1];
    const float* ea     = (const float*)d_in[2];
    const float* st     = (const float*)d_in[3];
    const float* lin1w  = (const float*)d_in[4];
    const float* lin1b  = (const float*)d_in[5];
    const float* mw1    = (const float*)d_in[6];
    const float* mb1    = (const float*)d_in[7];
    const float* mw2    = (const float*)d_in[8];
    const float* mb2    = (const float*)d_in[9];
    const float* cl1    = (const float*)d_in[10];
    const float* cl2    = (const float*)d_in[11];
    const float* cl2b   = (const float*)d_in[12];
    const float* outw   = (const float*)d_in[13];
    const float* outb   = (const float*)d_in[14];
    const int* eidx  = (const int*)d_in[15];
    const int* batch = (const int*)d_in[16];
    float* out = (float*)d_out;

    cudaFuncSetAttribute(node_gemm<0>, cudaFuncAttributeMaxDynamicSharedMemorySize, NODE_SMEM_BYTES);
    cudaFuncSetAttribute(node_gemm<1>, cudaFuncAttributeMaxDynamicSharedMemorySize, NODE_SMEM_BYTES);
    cudaFuncSetAttribute(node_gemm<2>, cudaFuncAttributeMaxDynamicSharedMemorySize, NODE_SMEM_BYTES);
    cudaFuncSetAttribute(node_gemm<3>, cudaFuncAttributeMaxDynamicSharedMemorySize, NODE_SMEM_BYTES);
    cudaFuncSetAttribute(edge_kernel,  cudaFuncAttributeMaxDynamicSharedMemorySize, EDGE_SMEM_BYTES);

    k_init<<<1, 256>>>(st);
    k_count<<<(NN + 255) / 256, 256>>>(batch);

    for (int i = 0; i < 2; i++) {
        const float* hin = (i == 0) ? h : (const float*)0;  // null => g_hbuf
        node_gemm<0><<<NB_NODE, NTHREADS, NODE_SMEM_BYTES>>>(
            hin, lin1w + i * 128 * 130, lin1b + i * 128, batch, (float*)0, 0);
        node_gemm<1><<<NB_NODE, NTHREADS, NODE_SMEM_BYTES>>>(
            (const float*)0, cl1 + i * 128 * 128, (const float*)0, batch, (float*)0, 0);
        k_reset<<<1, 32>>>();
        edge_kernel<<<EDGE_BLOCKS, ETHREADS, EDGE_SMEM_BYTES>>>(
            ea, ew, eidx, mw1 + i * 128 * 50, mb1 + i * 128,
            mw2 + i * 128 * 128, mb2 + i * 128);
        node_gemm<2><<<NB_NODE, NTHREADS, NODE_SMEM_BYTES>>>(
            (const float*)0, cl2 + i * 128 * 128, cl2b + i * 128, batch, (float*)0,
            (i == 0) ? 1 : 0);
        if (i == 0) k_state<<<1, 256>>>();
    }
    node_gemm<3><<<NB_NODE, NTHREADS, NODE_SMEM_BYTES>>>(
        (const float*)0, outw, outb, batch, out, 0);
}

// round 12
// speedup vs baseline: 1.4274x; 1.0761x over previous
#include <cuda_runtime.h>
#include <math.h>

#define NN 50000
#define EE 800000
#define HH 128
#define GG 50
#define FF 128
#define BB 256

#define TILE 128
#define PAD 132
#define NTHREADS 512
#define NB_NODE ((NN + TILE - 1) / TILE)   // 391
#define EDGE_BLOCKS 148
#define ETHREADS 384                       // 8 mma warps + 4 epilogue warps
#define NT2 (EE / 64)                      // 12500 64-edge tiles

typedef unsigned long long u64;

// ---------------- scratch -------------------------------------------------------
__device__ __align__(16) float g_h2[NN * HH];
__device__ __align__(16) float g_xf[NN * FF];
__device__ __align__(16) float g_agg[NN * FF];
__device__ __align__(16) float g_hbuf[NN * HH];
__device__ float g_state2[BB * 2];
__device__ float g_pool[BB];
__device__ float g_cnt[BB];

__device__ __forceinline__ float ssp(float x) {
    float sp = (x > 15.0f) ? x : log1pf(__expf(x));
    return sp - 0.69314718055994531f;
}

// ---- packed fp32x2 helpers (node GEMMs) ---------------------------------------
__device__ __forceinline__ u64 pk2(float v) {
    u64 r;
    unsigned u = __float_as_uint(v);
    asm("mov.b64 %0, {%1, %1};" : "=l"(r) : "r"(u));
    return r;
}
__device__ __forceinline__ float2 upk(u64 p) {
    unsigned lo, hi;
    asm("mov.b64 {%0, %1}, %2;" : "=r"(lo), "=r"(hi) : "l"(p));
    return make_float2(__uint_as_float(lo), __uint_as_float(hi));
}
#define FMA2(acc, a, b) \
    asm("fma.rn.f32x2 %0, %1, %2, %0;" : "+l"(acc) : "l"(a), "l"(b))

template <int K, int LD>
__device__ __forceinline__ void gemm_tile_p(const float* __restrict__ sW,
                                            const float* __restrict__ sX,
                                            int f0, int t0, u64 acc[16]) {
    const float* xp = sX + t0;
    const float* wp = sW + f0;
#pragma unroll 4
    for (int k = 0; k < K; k++) {
        float4 w4 = *(const float4*)wp;
        ulonglong2 A0 = *(const ulonglong2*)xp;
        ulonglong2 A1 = *(const ulonglong2*)(xp + 4);
        u64 wd0 = pk2(w4.x), wd1 = pk2(w4.y), wd2 = pk2(w4.z), wd3 = pk2(w4.w);
        FMA2(acc[0],  A0.x, wd0); FMA2(acc[1],  A0.x, wd1);
        FMA2(acc[2],  A0.x, wd2); FMA2(acc[3],  A0.x, wd3);
        FMA2(acc[4],  A0.y, wd0); FMA2(acc[5],  A0.y, wd1);
        FMA2(acc[6],  A0.y, wd2); FMA2(acc[7],  A0.y, wd3);
        FMA2(acc[8],  A1.x, wd0); FMA2(acc[9],  A1.x, wd1);
        FMA2(acc[10], A1.x, wd2); FMA2(acc[11], A1.x, wd3);
        FMA2(acc[12], A1.y, wd0); FMA2(acc[13], A1.y, wd1);
        FMA2(acc[14], A1.y, wd2); FMA2(acc[15], A1.y, wd3);
        xp += LD;
        wp += 128;
    }
}

// ---- tf32 mma helpers ----------------------------------------------------------
__device__ __forceinline__ float f2tf(float x) {
    unsigned r;
    asm("cvt.rna.tf32.f32 %0, %1;" : "=r"(r) : "f"(x));
    return __uint_as_float(r);
}
#define MMA_TF32(c, a, b) \
    asm volatile("mma.sync.aligned.m16n8k8.row.col.f32.tf32.tf32.f32 " \
        "{%0,%1,%2,%3}, {%4,%5,%6,%7}, {%8,%9}, {%0,%1,%2,%3};" \
        : "+f"((c)[0]), "+f"((c)[1]), "+f"((c)[2]), "+f"((c)[3]) \
        : "r"((a)[0]), "r"((a)[1]), "r"((a)[2]), "r"((a)[3]), \
          "r"((b)[0]), "r"((b)[1]))
#define BARX(id, n) asm volatile("bar.sync %0, %1;" :: "n"(id), "n"(n) : "memory")

// ---------------- small helper kernels -----------------------------------------
__global__ void k_init(const float* __restrict__ state_attr) {
    int b = blockIdx.x * blockDim.x + threadIdx.x;
    if (b < BB) {
        g_cnt[b] = 0.0f;
        g_pool[b] = 0.0f;
        g_state2[2 * b]     = state_attr[2 * b];
        g_state2[2 * b + 1] = state_attr[2 * b + 1];
    }
}
__global__ void k_count(const int* __restrict__ batch) {
    int n = blockIdx.x * blockDim.x + threadIdx.x;
    if (n < NN) atomicAdd(&g_cnt[batch[n]], 1.0f);
}
__global__ void k_state() {
    int b = threadIdx.x;
    if (b < BB) {
        float s = g_pool[b] / fmaxf(g_cnt[b], 1.0f);
        g_state2[2 * b]     = s;
        g_state2[2 * b + 1] = s;
        g_pool[b] = 0.0f;
    }
}

// ---------------- node GEMM kernel (unchanged champion config) -----------------
#define NODE_SMEM_FLOATS (17152 + TILE * PAD)
#define NODE_SMEM_BYTES  (NODE_SMEM_FLOATS * 4)

template <int MODE>
__global__ void __launch_bounds__(NTHREADS, 1)
node_gemm(const float* __restrict__ Xext, const float* __restrict__ W,
          const float* __restrict__ bias, const int* __restrict__ batch,
          float* __restrict__ Yext, int do_pool) {
    extern __shared__ float sm[];
    float* sW    = sm;
    float* sb    = sm + 16384;
    float* sw0   = sm + 16512;
    float* sw1   = sm + 16640;
    float* spool = sm + 16768;
    float* ssa0  = sm + 16896;
    float* ssa1  = sm + 17024;
    float* sX    = sm + 17152;

    const int tid = threadIdx.x;
    const int n0  = blockIdx.x * TILE;

    const float* X;
    float* Y;
    float* aux = 0;
    if (MODE == 0)      { X = Xext ? Xext : g_hbuf; Y = g_h2;   aux = g_agg; }
    else if (MODE == 1) { X = g_h2;                 Y = g_xf; }
    else if (MODE == 2) { X = g_agg;                Y = g_hbuf; aux = g_h2; }
    else                { X = g_hbuf;               Y = Yext; }

    constexpr int ldw  = (MODE == 0) ? 130 : 128;
    constexpr int woff = (MODE == 0) ? 2 : 0;

    for (int i = tid; i < 128 * 128; i += NTHREADS) {
        int f = i >> 7, k = i & 127;
        sW[k * 128 + f] = W[f * ldw + woff + k];
    }
    if (tid < 128) {
        sb[tid] = bias ? bias[tid] : 0.0f;
        spool[tid] = 0.0f;
        if (MODE == 0) {
            sw0[tid] = W[tid * 130];
            sw1[tid] = W[tid * 130 + 1];
            float a0 = 0.0f, a1 = 0.0f;
            int n = n0 + tid;
            if (n < NN) {
                int b = batch[n];
                a0 = g_state2[2 * b];
                a1 = g_state2[2 * b + 1];
            }
            ssa0[tid] = a0;
            ssa1[tid] = a1;
        }
    }
    for (int i = tid; i < TILE * 128; i += NTHREADS) {
        int t = i >> 7, k = i & 127;
        int n = n0 + t;
        sX[k * PAD + t] = (n < NN) ? X[(size_t)n * 128 + k] : 0.0f;
    }
    __syncthreads();

    const int f0 = (tid & 31) * 4;
    const int t0 = (tid >> 5) * 8;

    u64 acc[16];
    if (MODE == 1) {
#pragma unroll
        for (int i = 0; i < 16; i++) acc[i] = 0ull;
    } else {
#pragma unroll
        for (int fi = 0; fi < 4; fi++) {
            u64 bp = pk2(sb[f0 + fi]);
            acc[0 * 4 + fi] = bp;
            acc[1 * 4 + fi] = bp;
            acc[2 * 4 + fi] = bp;
            acc[3 * 4 + fi] = bp;
        }
    }

    if (MODE == 0) {
        ulonglong2 Sa = *(const ulonglong2*)&ssa0[t0];
        ulonglong2 Sb = *(const ulonglong2*)&ssa0[t0 + 4];
        ulonglong2 Ta = *(const ulonglong2*)&ssa1[t0];
        ulonglong2 Tb = *(const ulonglong2*)&ssa1[t0 + 4];
#pragma unroll
        for (int fi = 0; fi < 4; fi++) {
            u64 w0d = pk2(sw0[f0 + fi]);
            u64 w1d = pk2(sw1[f0 + fi]);
            FMA2(acc[0 * 4 + fi], Sa.x, w0d);
            FMA2(acc[1 * 4 + fi], Sa.y, w0d);
            FMA2(acc[2 * 4 + fi], Sb.x, w0d);
            FMA2(acc[3 * 4 + fi], Sb.y, w0d);
            FMA2(acc[0 * 4 + fi], Ta.x, w1d);
            FMA2(acc[1 * 4 + fi], Ta.y, w1d);
            FMA2(acc[2 * 4 + fi], Tb.x, w1d);
            FMA2(acc[3 * 4 + fi], Tb.y, w1d);
        }
    }

    gemm_tile_p<128, PAD>(sW, sX, f0, t0, acc);

#pragma unroll
    for (int tp = 0; tp < 4; tp++) {
        float2 p0 = upk(acc[tp * 4 + 0]);
        float2 p1 = upk(acc[tp * 4 + 1]);
        float2 p2 = upk(acc[tp * 4 + 2]);
        float2 p3 = upk(acc[tp * 4 + 3]);
        float4 v[2];
        v[0] = make_float4(p0.x, p1.x, p2.x, p3.x);
        v[1] = make_float4(p0.y, p1.y, p2.y, p3.y);
#pragma unroll
        for (int hh = 0; hh < 2; hh++) {
            int t = t0 + 2 * tp + hh;
            int n = n0 + t;
            if (n >= NN) continue;
            size_t off = (size_t)n * 128 + f0;
            if (MODE == 0) {
                *(float4*)&Y[off]   = v[hh];
                *(float4*)&aux[off] = make_float4(0.f, 0.f, 0.f, 0.f);
            } else if (MODE == 2) {
                float4 h2v = *(const float4*)&aux[off];
                float4 o;
                o.x = h2v.x + ssp(v[hh].x);
                o.y = h2v.y + ssp(v[hh].y);
                o.z = h2v.z + ssp(v[hh].z);
                o.w = h2v.w + ssp(v[hh].w);
                *(float4*)&Y[off] = o;
                if (do_pool) atomicAdd(&spool[t], o.x + o.y + o.z + o.w);
            } else {
                *(float4*)&Y[off] = v[hh];
            }
        }
    }

    if (MODE == 2 && do_pool) {
        __syncthreads();
        if (tid < TILE) {
            int n = n0 + tid;
            if (n < NN) atomicAdd(&g_pool[batch[n]], spool[tid]);
        }
    }
}

// ---------------- edge kernel: warp-specialized mma/LSU pipeline ---------------
// smem float offsets
#define SW1P 0        // 7168  W1 b-frags (K padded to 56)
#define SW2P 7168     // 16384 W2 b-frags
#define SZB  23552    // 8448  z tile 64x132
#define SOUT 32000    // 8448  out tile 64x132
#define SF0  40448    // 4032  FILL buffer 0
#define SF1  44480    // 4032  FILL buffer 1
#define SB1V 48512
#define SB2V 48640
#define ESM_FLOATS 48768
#define ESM_BYTES (ESM_FLOATS * 4)
// FILL sublayout (floats)
#define FEA  0        // 64*60 ea tile
#define FC   3840     // 64 cutoff
#define FSRC 3904     // 64 src (int)
#define FDST 3968     // 64 dst (int)

__device__ __forceinline__ void edge_fill(float* __restrict__ F, int e0, int et,
                                          const float* __restrict__ ea,
                                          const float* __restrict__ ew,
                                          const int* __restrict__ eidx) {
    for (int i = et; i < 64 * 30; i += 128) {
        int e = i / 30, j = i - e * 30;
        float2 v = make_float2(0.0f, 0.0f);
        if (j < 25) v = *(const float2*)(ea + (size_t)(e0 + e) * GG + 2 * j);
        v.x = f2tf(v.x);
        v.y = f2tf(v.y);
        *(float2*)&F[FEA + e * 60 + 2 * j] = v;
    }
    if (et < 64) {
        int e = e0 + et;
        F[FC + et] = 0.5f * (__cosf(ew[e] * 0.62831853071795864769f) + 1.0f);
        ((int*)F)[FSRC + et] = eidx[e];
        ((int*)F)[FDST + et] = eidx[EE + e];
    }
}

__device__ __forceinline__ void edge_scatter(const float* __restrict__ sm_,
                                             const float* __restrict__ Fm, int et) {
    int e  = et >> 1;
    int fh = (et & 1) * 64;
    float c = Fm[FC + e];
    int s = ((const int*)Fm)[FSRC + e];
    int d = ((const int*)Fm)[FDST + e];
    const float* orow = sm_ + SOUT + e * 132 + fh;
    const float* xb = g_xf + (size_t)s * 128 + fh;
    float* ab = g_agg + (size_t)d * 128 + fh;
#pragma unroll
    for (int q = 0; q < 16; q++) {
        float4 v = *(const float4*)(orow + 4 * q);
        float4 x = *(const float4*)(xb + 4 * q);
        float mx = v.x * c * x.x;
        float my = v.y * c * x.y;
        float mz = v.z * c * x.z;
        float mw = v.w * c * x.w;
        asm volatile("red.global.add.v4.f32 [%0], {%1, %2, %3, %4};"
                     :: "l"(ab + 4 * q), "f"(mx), "f"(my), "f"(mz), "f"(mw)
                     : "memory");
    }
}

__global__ void __launch_bounds__(ETHREADS, 1)
edge_kernel(const float* __restrict__ ea, const float* __restrict__ ew,
            const int* __restrict__ eidx,
            const float* __restrict__ W1, const float* __restrict__ b1,
            const float* __restrict__ W2, const float* __restrict__ b2) {
    extern __shared__ float sm[];
    const int tid  = threadIdx.x;
    const int wid  = tid >> 5;
    const int lane = tid & 31;

    // pack weights (all threads)
    for (int i = tid; i < 128 * 56; i += ETHREADS) {
        int f = i / 56, k = i - f * 56;
        float v = (k < GG) ? W1[f * GG + k] : 0.0f;
        int idx = (((k >> 3) * 16 + (f >> 3)) * 32 + (f & 7) * 4 + (k & 3)) * 2 + ((k & 7) >> 2);
        sm[SW1P + idx] = f2tf(v);
    }
    for (int i = tid; i < 128 * 128; i += ETHREADS) {
        int f = i >> 7, k = i & 127;
        int idx = (((k >> 3) * 16 + (f >> 3)) * 32 + (f & 7) * 4 + (k & 3)) * 2 + ((k & 7) >> 2);
        sm[SW2P + idx] = f2tf(W2[i]);
    }
    if (tid < 128) {
        sm[SB1V + tid] = b1[tid];
        sm[SB2V + tid] = b2[tid];
    }
    __syncthreads();

    const bool is_mma = (wid < 8);
    int it = 0;

    if (!is_mma)
        edge_fill(sm + SF0, blockIdx.x * 64, tid - 256, ea, ew, eidx);
    BARX(3, 384);

    for (int t = blockIdx.x; t < NT2; t += EDGE_BLOCKS, it++) {
        float* F  = sm + ((it & 1) ? SF1 : SF0);   // current tile
        float* Fp = sm + ((it & 1) ? SF0 : SF1);   // prev meta / next fill
        if (is_mma) {
            const int g = lane >> 2, tg = lane & 3;
            const int mq = wid >> 1, nh = wid & 1;
            const int r0 = mq * 16;
            float acc[8][4];
#pragma unroll
            for (int nb = 0; nb < 8; nb++)
#pragma unroll
                for (int q = 0; q < 4; q++) acc[nb][q] = 0.0f;

            // stage 1: K=56 (7 chunks)
#pragma unroll
            for (int kc = 0; kc < 7; kc++) {
                unsigned a[4];
                const float* p = F + FEA + (r0 + g) * 60 + kc * 8 + tg;
                a[0] = __float_as_uint(p[0]);
                a[1] = __float_as_uint(p[8 * 60]);
                a[2] = __float_as_uint(p[4]);
                a[3] = __float_as_uint(p[8 * 60 + 4]);
#pragma unroll
                for (int nb = 0; nb < 8; nb++) {
                    float2 bb = *(const float2*)&sm[SW1P + ((kc * 16 + nh * 8 + nb) * 32 + lane) * 2];
                    unsigned b[2] = {__float_as_uint(bb.x), __float_as_uint(bb.y)};
                    MMA_TF32(acc[nb], a, b);
                }
            }
            // z = f2tf(ssp(acc + b1))
#pragma unroll
            for (int nb = 0; nb < 8; nb++) {
                int col = nh * 64 + nb * 8 + 2 * tg;
                float bv0 = sm[SB1V + col], bv1 = sm[SB1V + col + 1];
                float2 lo, hi;
                lo.x = f2tf(ssp(acc[nb][0] + bv0));
                lo.y = f2tf(ssp(acc[nb][1] + bv1));
                hi.x = f2tf(ssp(acc[nb][2] + bv0));
                hi.y = f2tf(ssp(acc[nb][3] + bv1));
                *(float2*)&sm[SZB + (r0 + g) * 132 + col]     = lo;
                *(float2*)&sm[SZB + (r0 + g + 8) * 132 + col] = hi;
            }
            BARX(1, 256);

            // stage 2: K=128 (16 chunks)
#pragma unroll
            for (int nb = 0; nb < 8; nb++)
#pragma unroll
                for (int q = 0; q < 4; q++) acc[nb][q] = 0.0f;
#pragma unroll 4
            for (int kc = 0; kc < 16; kc++) {
                unsigned a[4];
                const float* p = sm + SZB + (r0 + g) * 132 + kc * 8 + tg;
                a[0] = __float_as_uint(p[0]);
                a[1] = __float_as_uint(p[8 * 132]);
                a[2] = __float_as_uint(p[4]);
                a[3] = __float_as_uint(p[8 * 132 + 4]);
#pragma unroll
                for (int nb = 0; nb < 8; nb++) {
                    float2 bb = *(const float2*)&sm[SW2P + ((kc * 16 + nh * 8 + nb) * 32 + lane) * 2];
                    unsigned b[2] = {__float_as_uint(bb.x), __float_as_uint(bb.y)};
                    MMA_TF32(acc[nb], a, b);
                }
            }
            BARX(2, 384);   // wait: previous OUT fully scattered
            // OUT = acc + b2
#pragma unroll
            for (int nb = 0; nb < 8; nb++) {
                int col = nh * 64 + nb * 8 + 2 * tg;
                float bv0 = sm[SB2V + col], bv1 = sm[SB2V + col + 1];
                float2 lo, hi;
                lo.x = acc[nb][0] + bv0;
                lo.y = acc[nb][1] + bv1;
                hi.x = acc[nb][2] + bv0;
                hi.y = acc[nb][3] + bv1;
                *(float2*)&sm[SOUT + (r0 + g) * 132 + col]     = lo;
                *(float2*)&sm[SOUT + (r0 + g + 8) * 132 + col] = hi;
            }
        } else {
            int et = tid - 256;
            if (it > 0) edge_scatter(sm, Fp, et);   // scatter tile t-1
            BARX(2, 384);
            int tn = t + EDGE_BLOCKS;
            if (tn < NT2) edge_fill(Fp, tn * 64, et, ea, ew, eidx);
        }
        BARX(3, 384);   // OUT(t) ready + FILL(t+1) ready
    }

    if (!is_mma && it > 0) {
        float* Fl = sm + (((it - 1) & 1) ? SF1 : SF0);
        edge_scatter(sm, Fl, tid - 256);
    }
}

// ---------------- launcher -----------------------------------------------------
extern "C" void kernel_launch(void* const* d_in, const int* in_sizes, int n_in,
                              void* d_out, int out_size) {
    const float* h      = (const float*)d_in[0];
    const float* ew     = (const float*)d_in[1];
    const float* ea     = (const float*)d_in[2];
    const float* st     = (const float*)d_in[3];
    const float* lin1w  = (const float*)d_in[4];
    const float* lin1b  = (const float*)d_in[5];
    const float* mw1    = (const float*)d_in[6];
    const float* mb1    = (const float*)d_in[7];
    const float* mw2    = (const float*)d_in[8];
    const float* mb2    = (const float*)d_in[9];
    const float* cl1    = (const float*)d_in[10];
    const float* cl2    = (const float*)d_in[11];
    const float* cl2b   = (const float*)d_in[12];
    const float* outw   = (const float*)d_in[13];
    const float* outb   = (const float*)d_in[14];
    const int* eidx  = (const int*)d_in[15];
    const int* batch = (const int*)d_in[16];
    float* out = (float*)d_out;

    cudaFuncSetAttribute(node_gemm<0>, cudaFuncAttributeMaxDynamicSharedMemorySize, NODE_SMEM_BYTES);
    cudaFuncSetAttribute(node_gemm<1>, cudaFuncAttributeMaxDynamicSharedMemorySize, NODE_SMEM_BYTES);
    cudaFuncSetAttribute(node_gemm<2>, cudaFuncAttributeMaxDynamicSharedMemorySize, NODE_SMEM_BYTES);
    cudaFuncSetAttribute(node_gemm<3>, cudaFuncAttributeMaxDynamicSharedMemorySize, NODE_SMEM_BYTES);
    cudaFuncSetAttribute(edge_kernel,  cudaFuncAttributeMaxDynamicSharedMemorySize, ESM_BYTES);

    k_init<<<1, 256>>>(st);
    k_count<<<(NN + 255) / 256, 256>>>(batch);

    for (int i = 0; i < 2; i++) {
        const float* hin = (i == 0) ? h : (const float*)0;  // null => g_hbuf
        node_gemm<0><<<NB_NODE, NTHREADS, NODE_SMEM_BYTES>>>(
            hin, lin1w + i * 128 * 130, lin1b + i * 128, batch, (float*)0, 0);
        node_gemm<1><<<NB_NODE, NTHREADS, NODE_SMEM_BYTES>>>(
            (const float*)0, cl1 + i * 128 * 128, (const float*)0, batch, (float*)0, 0);
        edge_kernel<<<EDGE_BLOCKS, ETHREADS, ESM_BYTES>>>(
            ea, ew, eidx, mw1 + i * 128 * 50, mb1 + i * 128,
            mw2 + i * 128 * 128, mb2 + i * 128);
        node_gemm<2><<<NB_NODE, NTHREADS, NODE_SMEM_BYTES>>>(
            (const float*)0, cl2 + i * 128 * 128, cl2b + i * 128, batch, (float*)0,
            (i == 0) ? 1 : 0);
        if (i == 0) k_state<<<1, 256>>>();
    }
    node_gemm<3><<<NB_NODE, NTHREADS, NODE_SMEM_BYTES>>>(
        (const float*)0, outw, outb, batch, out, 0);
}

// round 13
// speedup vs baseline: 1.5082x; 1.0566x over previous
#include <cuda_runtime.h>
#include <math.h>

#define NN 50000
#define EE 800000
#define HH 128
#define GG 50
#define FF 128
#define BB 256

#define TILE 128
#define PAD 132
#define NTHREADS 512
#define NB_NODE ((NN + TILE - 1) / TILE)   // 391
#define EDGE_BLOCKS 148
#define ETHREADS 384                       // 8 mma warps + 4 epilogue warps
#define NT2 (EE / 64)                      // 12500 64-edge tiles

typedef unsigned long long u64;

// ---------------- scratch -------------------------------------------------------
__device__ __align__(16) float g_h2[NN * HH];
__device__ __align__(16) float g_xf[NN * FF];
__device__ __align__(16) float g_agg[NN * FF];
__device__ __align__(16) float g_hbuf[NN * HH];
__device__ float g_state2[BB * 2];
__device__ float g_pool[BB];
__device__ float g_cnt[BB];

__device__ __forceinline__ float ssp(float x) {
    float sp = (x > 15.0f) ? x : log1pf(__expf(x));
    return sp - 0.69314718055994531f;
}

// ---- packed fp32x2 helpers (node GEMMs) ---------------------------------------
__device__ __forceinline__ u64 pk2(float v) {
    u64 r;
    unsigned u = __float_as_uint(v);
    asm("mov.b64 %0, {%1, %1};" : "=l"(r) : "r"(u));
    return r;
}
__device__ __forceinline__ float2 upk(u64 p) {
    unsigned lo, hi;
    asm("mov.b64 {%0, %1}, %2;" : "=r"(lo), "=r"(hi) : "l"(p));
    return make_float2(__uint_as_float(lo), __uint_as_float(hi));
}
#define FMA2(acc, a, b) \
    asm("fma.rn.f32x2 %0, %1, %2, %0;" : "+l"(acc) : "l"(a), "l"(b))

template <int K, int LD>
__device__ __forceinline__ void gemm_tile_p(const float* __restrict__ sW,
                                            const float* __restrict__ sX,
                                            int f0, int t0, u64 acc[16]) {
    const float* xp = sX + t0;
    const float* wp = sW + f0;
#pragma unroll 4
    for (int k = 0; k < K; k++) {
        float4 w4 = *(const float4*)wp;
        ulonglong2 A0 = *(const ulonglong2*)xp;
        ulonglong2 A1 = *(const ulonglong2*)(xp + 4);
        u64 wd0 = pk2(w4.x), wd1 = pk2(w4.y), wd2 = pk2(w4.z), wd3 = pk2(w4.w);
        FMA2(acc[0],  A0.x, wd0); FMA2(acc[1],  A0.x, wd1);
        FMA2(acc[2],  A0.x, wd2); FMA2(acc[3],  A0.x, wd3);
        FMA2(acc[4],  A0.y, wd0); FMA2(acc[5],  A0.y, wd1);
        FMA2(acc[6],  A0.y, wd2); FMA2(acc[7],  A0.y, wd3);
        FMA2(acc[8],  A1.x, wd0); FMA2(acc[9],  A1.x, wd1);
        FMA2(acc[10], A1.x, wd2); FMA2(acc[11], A1.x, wd3);
        FMA2(acc[12], A1.y, wd0); FMA2(acc[13], A1.y, wd1);
        FMA2(acc[14], A1.y, wd2); FMA2(acc[15], A1.y, wd3);
        xp += LD;
        wp += 128;
    }
}

// ---- tf32 mma helpers ----------------------------------------------------------
__device__ __forceinline__ float f2tf(float x) {
    unsigned r;
    asm("cvt.rna.tf32.f32 %0, %1;" : "=r"(r) : "f"(x));
    return __uint_as_float(r);
}
#define MMA_TF32(c, a, b) \
    asm volatile("mma.sync.aligned.m16n8k8.row.col.f32.tf32.tf32.f32 " \
        "{%0,%1,%2,%3}, {%4,%5,%6,%7}, {%8,%9}, {%0,%1,%2,%3};" \
        : "+f"((c)[0]), "+f"((c)[1]), "+f"((c)[2]), "+f"((c)[3]) \
        : "r"((a)[0]), "r"((a)[1]), "r"((a)[2]), "r"((a)[3]), \
          "r"((b)[0]), "r"((b)[1]))
#define BARX(id, n) asm volatile("bar.sync %0, %1;" :: "n"(id), "n"(n) : "memory")

// ---------------- small helper kernels -----------------------------------------
__global__ void k_init(const float* __restrict__ state_attr) {
    int b = blockIdx.x * blockDim.x + threadIdx.x;
    if (b < BB) {
        g_cnt[b] = 0.0f;
        g_pool[b] = 0.0f;
        g_state2[2 * b]     = state_attr[2 * b];
        g_state2[2 * b + 1] = state_attr[2 * b + 1];
    }
}
__global__ void k_count(const int* __restrict__ batch) {
    int n = blockIdx.x * blockDim.x + threadIdx.x;
    if (n < NN) atomicAdd(&g_cnt[batch[n]], 1.0f);
}
__global__ void k_state() {
    int b = threadIdx.x;
    if (b < BB) {
        float s = g_pool[b] / fmaxf(g_cnt[b], 1.0f);
        g_state2[2 * b]     = s;
        g_state2[2 * b + 1] = s;
        g_pool[b] = 0.0f;
    }
}

// ---------------- node GEMM kernel (unchanged champion config) -----------------
#define NODE_SMEM_FLOATS (17152 + TILE * PAD)
#define NODE_SMEM_BYTES  (NODE_SMEM_FLOATS * 4)

template <int MODE>
__global__ void __launch_bounds__(NTHREADS, 1)
node_gemm(const float* __restrict__ Xext, const float* __restrict__ W,
          const float* __restrict__ bias, const int* __restrict__ batch,
          float* __restrict__ Yext, int do_pool) {
    extern __shared__ float sm[];
    float* sW    = sm;
    float* sb    = sm + 16384;
    float* sw0   = sm + 16512;
    float* sw1   = sm + 16640;
    float* spool = sm + 16768;
    float* ssa0  = sm + 16896;
    float* ssa1  = sm + 17024;
    float* sX    = sm + 17152;

    const int tid = threadIdx.x;
    const int n0  = blockIdx.x * TILE;

    const float* X;
    float* Y;
    float* aux = 0;
    if (MODE == 0)      { X = Xext ? Xext : g_hbuf; Y = g_h2;   aux = g_agg; }
    else if (MODE == 1) { X = g_h2;                 Y = g_xf; }
    else if (MODE == 2) { X = g_agg;                Y = g_hbuf; aux = g_h2; }
    else                { X = g_hbuf;               Y = Yext; }

    constexpr int ldw  = (MODE == 0) ? 130 : 128;
    constexpr int woff = (MODE == 0) ? 2 : 0;

    for (int i = tid; i < 128 * 128; i += NTHREADS) {
        int f = i >> 7, k = i & 127;
        sW[k * 128 + f] = W[f * ldw + woff + k];
    }
    if (tid < 128) {
        sb[tid] = bias ? bias[tid] : 0.0f;
        spool[tid] = 0.0f;
        if (MODE == 0) {
            sw0[tid] = W[tid * 130];
            sw1[tid] = W[tid * 130 + 1];
            float a0 = 0.0f, a1 = 0.0f;
            int n = n0 + tid;
            if (n < NN) {
                int b = batch[n];
                a0 = g_state2[2 * b];
                a1 = g_state2[2 * b + 1];
            }
            ssa0[tid] = a0;
            ssa1[tid] = a1;
        }
    }
    for (int i = tid; i < TILE * 128; i += NTHREADS) {
        int t = i >> 7, k = i & 127;
        int n = n0 + t;
        sX[k * PAD + t] = (n < NN) ? X[(size_t)n * 128 + k] : 0.0f;
    }
    __syncthreads();

    const int f0 = (tid & 31) * 4;
    const int t0 = (tid >> 5) * 8;

    u64 acc[16];
    if (MODE == 1) {
#pragma unroll
        for (int i = 0; i < 16; i++) acc[i] = 0ull;
    } else {
#pragma unroll
        for (int fi = 0; fi < 4; fi++) {
            u64 bp = pk2(sb[f0 + fi]);
            acc[0 * 4 + fi] = bp;
            acc[1 * 4 + fi] = bp;
            acc[2 * 4 + fi] = bp;
            acc[3 * 4 + fi] = bp;
        }
    }

    if (MODE == 0) {
        ulonglong2 Sa = *(const ulonglong2*)&ssa0[t0];
        ulonglong2 Sb = *(const ulonglong2*)&ssa0[t0 + 4];
        ulonglong2 Ta = *(const ulonglong2*)&ssa1[t0];
        ulonglong2 Tb = *(const ulonglong2*)&ssa1[t0 + 4];
#pragma unroll
        for (int fi = 0; fi < 4; fi++) {
            u64 w0d = pk2(sw0[f0 + fi]);
            u64 w1d = pk2(sw1[f0 + fi]);
            FMA2(acc[0 * 4 + fi], Sa.x, w0d);
            FMA2(acc[1 * 4 + fi], Sa.y, w0d);
            FMA2(acc[2 * 4 + fi], Sb.x, w0d);
            FMA2(acc[3 * 4 + fi], Sb.y, w0d);
            FMA2(acc[0 * 4 + fi], Ta.x, w1d);
            FMA2(acc[1 * 4 + fi], Ta.y, w1d);
            FMA2(acc[2 * 4 + fi], Tb.x, w1d);
            FMA2(acc[3 * 4 + fi], Tb.y, w1d);
        }
    }

    gemm_tile_p<128, PAD>(sW, sX, f0, t0, acc);

#pragma unroll
    for (int tp = 0; tp < 4; tp++) {
        float2 p0 = upk(acc[tp * 4 + 0]);
        float2 p1 = upk(acc[tp * 4 + 1]);
        float2 p2 = upk(acc[tp * 4 + 2]);
        float2 p3 = upk(acc[tp * 4 + 3]);
        float4 v[2];
        v[0] = make_float4(p0.x, p1.x, p2.x, p3.x);
        v[1] = make_float4(p0.y, p1.y, p2.y, p3.y);
#pragma unroll
        for (int hh = 0; hh < 2; hh++) {
            int t = t0 + 2 * tp + hh;
            int n = n0 + t;
            if (n >= NN) continue;
            size_t off = (size_t)n * 128 + f0;
            if (MODE == 0) {
                *(float4*)&Y[off]   = v[hh];
                *(float4*)&aux[off] = make_float4(0.f, 0.f, 0.f, 0.f);
            } else if (MODE == 2) {
                float4 h2v = *(const float4*)&aux[off];
                float4 o;
                o.x = h2v.x + ssp(v[hh].x);
                o.y = h2v.y + ssp(v[hh].y);
                o.z = h2v.z + ssp(v[hh].z);
                o.w = h2v.w + ssp(v[hh].w);
                *(float4*)&Y[off] = o;
                if (do_pool) atomicAdd(&spool[t], o.x + o.y + o.z + o.w);
            } else {
                *(float4*)&Y[off] = v[hh];
            }
        }
    }

    if (MODE == 2 && do_pool) {
        __syncthreads();
        if (tid < TILE) {
            int n = n0 + tid;
            if (n < NN) atomicAdd(&g_pool[batch[n]], spool[tid]);
        }
    }
}

// ---------------- edge kernel: decoupled warp-specialized pipeline -------------
// smem float offsets
#define SW1P  0        // 7168  W1 b-frags (K padded to 56)
#define SW2P  7168     // 16384 W2 b-frags
#define SZB   23552    // 8448  z tile 64x132 (mma-internal)
#define SOUT0 32000    // 8448  out buffer 0
#define SOUT1 40448    // 8448  out buffer 1
#define SF0   48896    // 4032  FILL buffer 0 (ea + meta)
#define SF1   52928    // 4032  FILL buffer 1
#define SB1V  56960
#define SB2V  57088
#define ESM_FLOATS 57216
#define ESM_BYTES (ESM_FLOATS * 4)   // 228864 B
// FILL sublayout (floats)
#define FEA  0        // 64*60 ea tile
#define FC   3840     // 64 cutoff
#define FSRC 3904     // 64 src (int)
#define FDST 3968     // 64 dst (int)

__device__ __forceinline__ void edge_fill(float* __restrict__ F, int e0, int et,
                                          const float* __restrict__ ea,
                                          const float* __restrict__ ew,
                                          const int* __restrict__ eidx) {
    for (int i = et; i < 64 * 30; i += 128) {
        int e = i / 30, j = i - e * 30;
        float2 v = make_float2(0.0f, 0.0f);
        if (j < 25) v = *(const float2*)(ea + (size_t)(e0 + e) * GG + 2 * j);
        v.x = f2tf(v.x);
        v.y = f2tf(v.y);
        *(float2*)&F[FEA + e * 60 + 2 * j] = v;
    }
    if (et < 64) {
        int e = e0 + et;
        F[FC + et] = 0.5f * (__cosf(ew[e] * 0.62831853071795864769f) + 1.0f);
        ((int*)F)[FSRC + et] = eidx[e];
        ((int*)F)[FDST + et] = eidx[EE + e];
    }
}

__device__ __forceinline__ void edge_scatter(const float* __restrict__ OUTb,
                                             const float* __restrict__ Fm, int et) {
    int e  = et >> 1;
    int fh = (et & 1) * 64;
    float c = Fm[FC + e];
    int s = ((const int*)Fm)[FSRC + e];
    int d = ((const int*)Fm)[FDST + e];
    const float* orow = OUTb + e * 132 + fh;
    const float* xb = g_xf + (size_t)s * 128 + fh;
    float* ab = g_agg + (size_t)d * 128 + fh;
#pragma unroll
    for (int q = 0; q < 16; q++) {
        float4 v = *(const float4*)(orow + 4 * q);
        float4 x = *(const float4*)(xb + 4 * q);
        float mx = v.x * c * x.x;
        float my = v.y * c * x.y;
        float mz = v.z * c * x.z;
        float mw = v.w * c * x.w;
        asm volatile("red.global.add.v4.f32 [%0], {%1, %2, %3, %4};"
                     :: "l"(ab + 4 * q), "f"(mx), "f"(my), "f"(mz), "f"(mw)
                     : "memory");
    }
}

__global__ void __launch_bounds__(ETHREADS, 1)
edge_kernel(const float* __restrict__ ea, const float* __restrict__ ew,
            const int* __restrict__ eidx,
            const float* __restrict__ W1, const float* __restrict__ b1,
            const float* __restrict__ W2, const float* __restrict__ b2) {
    extern __shared__ float sm[];
    const int tid  = threadIdx.x;
    const int wid  = tid >> 5;
    const int lane = tid & 31;

    for (int i = tid; i < 128 * 56; i += ETHREADS) {
        int f = i / 56, k = i - f * 56;
        float v = (k < GG) ? W1[f * GG + k] : 0.0f;
        int idx = (((k >> 3) * 16 + (f >> 3)) * 32 + (f & 7) * 4 + (k & 3)) * 2 + ((k & 7) >> 2);
        sm[SW1P + idx] = f2tf(v);
    }
    for (int i = tid; i < 128 * 128; i += ETHREADS) {
        int f = i >> 7, k = i & 127;
        int idx = (((k >> 3) * 16 + (f >> 3)) * 32 + (f & 7) * 4 + (k & 3)) * 2 + ((k & 7) >> 2);
        sm[SW2P + idx] = f2tf(W2[i]);
    }
    if (tid < 128) {
        sm[SB1V + tid] = b1[tid];
        sm[SB2V + tid] = b2[tid];
    }
    __syncthreads();

    const bool is_mma = (wid < 8);
    int it = 0;

    if (!is_mma)
        edge_fill(sm + SF0, blockIdx.x * 64, tid - 256, ea, ew, eidx);
    BARX(3, 384);

    for (int t = blockIdx.x; t < NT2; t += EDGE_BLOCKS, it++) {
        float* F    = sm + ((it & 1) ? SF1 : SF0);
        float* OUTc = sm + ((it & 1) ? SOUT1 : SOUT0);
        if (is_mma) {
            const int g = lane >> 2, tg = lane & 3;
            const int mq = wid >> 1, nh = wid & 1;
            const int r0 = mq * 16;
            float acc[8][4];
#pragma unroll
            for (int nb = 0; nb < 8; nb++)
#pragma unroll
                for (int q = 0; q < 4; q++) acc[nb][q] = 0.0f;

            // stage 1: K=56 (7 chunks)
#pragma unroll
            for (int kc = 0; kc < 7; kc++) {
                unsigned a[4];
                const float* p = F + FEA + (r0 + g) * 60 + kc * 8 + tg;
                a[0] = __float_as_uint(p[0]);
                a[1] = __float_as_uint(p[8 * 60]);
                a[2] = __float_as_uint(p[4]);
                a[3] = __float_as_uint(p[8 * 60 + 4]);
#pragma unroll
                for (int nb = 0; nb < 8; nb++) {
                    float2 bb = *(const float2*)&sm[SW1P + ((kc * 16 + nh * 8 + nb) * 32 + lane) * 2];
                    unsigned b[2] = {__float_as_uint(bb.x), __float_as_uint(bb.y)};
                    MMA_TF32(acc[nb], a, b);
                }
            }
            // z = f2tf(ssp(acc + b1))
#pragma unroll
            for (int nb = 0; nb < 8; nb++) {
                int col = nh * 64 + nb * 8 + 2 * tg;
                float bv0 = sm[SB1V + col], bv1 = sm[SB1V + col + 1];
                float2 lo, hi;
                lo.x = f2tf(ssp(acc[nb][0] + bv0));
                lo.y = f2tf(ssp(acc[nb][1] + bv1));
                hi.x = f2tf(ssp(acc[nb][2] + bv0));
                hi.y = f2tf(ssp(acc[nb][3] + bv1));
                *(float2*)&sm[SZB + (r0 + g) * 132 + col]     = lo;
                *(float2*)&sm[SZB + (r0 + g + 8) * 132 + col] = hi;
            }
            BARX(1, 256);

            // stage 2: K=128 (16 chunks)
#pragma unroll
            for (int nb = 0; nb < 8; nb++)
#pragma unroll
                for (int q = 0; q < 4; q++) acc[nb][q] = 0.0f;
#pragma unroll 4
            for (int kc = 0; kc < 16; kc++) {
                unsigned a[4];
                const float* p = sm + SZB + (r0 + g) * 132 + kc * 8 + tg;
                a[0] = __float_as_uint(p[0]);
                a[1] = __float_as_uint(p[8 * 132]);
                a[2] = __float_as_uint(p[4]);
                a[3] = __float_as_uint(p[8 * 132 + 4]);
#pragma unroll
                for (int nb = 0; nb < 8; nb++) {
                    float2 bb = *(const float2*)&sm[SW2P + ((kc * 16 + nh * 8 + nb) * 32 + lane) * 2];
                    unsigned b[2] = {__float_as_uint(bb.x), __float_as_uint(bb.y)};
                    MMA_TF32(acc[nb], a, b);
                }
            }
            // OUT(t) = acc + b2  (buffer disjoint from scatter's OUT(t-1))
#pragma unroll
            for (int nb = 0; nb < 8; nb++) {
                int col = nh * 64 + nb * 8 + 2 * tg;
                float bv0 = sm[SB2V + col], bv1 = sm[SB2V + col + 1];
                float2 lo, hi;
                lo.x = acc[nb][0] + bv0;
                lo.y = acc[nb][1] + bv1;
                hi.x = acc[nb][2] + bv0;
                hi.y = acc[nb][3] + bv1;
                *(float2*)&OUTc[(r0 + g) * 132 + col]     = lo;
                *(float2*)&OUTc[(r0 + g + 8) * 132 + col] = hi;
            }
        } else {
            int et = tid - 256;
            if (it > 0) {
                float* Fp   = sm + ((it & 1) ? SF0 : SF1);
                float* OUTp = sm + ((it & 1) ? SOUT0 : SOUT1);
                edge_scatter(OUTp, Fp, et);     // scatter tile t-1
            }
            BARX(4, 128);                       // meta read done before refill
            int tn = t + EDGE_BLOCKS;
            if (tn < NT2)
                edge_fill(sm + ((it & 1) ? SF0 : SF1), tn * 64, et, ea, ew, eidx);
        }
        BARX(3, 384);   // OUT(t) ready; FILL(t+1) ready; scatter(t-1) done
    }

    if (!is_mma && it > 0) {
        float* Fl   = sm + (((it - 1) & 1) ? SF1 : SF0);
        float* OUTl = sm + (((it - 1) & 1) ? SOUT1 : SOUT0);
        edge_scatter(OUTl, Fl, tid - 256);
    }
}

// ---------------- launcher -----------------------------------------------------
extern "C" void kernel_launch(void* const* d_in, const int* in_sizes, int n_in,
                              void* d_out, int out_size) {
    const float* h      = (const float*)d_in[0];
    const float* ew     = (const float*)d_in[1];
    const float* ea     = (const float*)d_in[2];
    const float* st     = (const float*)d_in[3];
    const float* lin1w  = (const float*)d_in[4];
    const float* lin1b  = (const float*)d_in[5];
    const float* mw1    = (const float*)d_in[6];
    const float* mb1    = (const float*)d_in[7];
    const float* mw2    = (const float*)d_in[8];
    const float* mb2    = (const float*)d_in[9];
    const float* cl1    = (const float*)d_in[10];
    const float* cl2    = (const float*)d_in[11];
    const float* cl2b   = (const float*)d_in[12];
    const float* outw   = (const float*)d_in[13];
    const float* outb   = (const float*)d_in[14];
    const int* eidx  = (const int*)d_in[15];
    const int* batch = (const int*)d_in[16];
    float* out = (float*)d_out;

    cudaFuncSetAttribute(node_gemm<0>, cudaFuncAttributeMaxDynamicSharedMemorySize, NODE_SMEM_BYTES);
    cudaFuncSetAttribute(node_gemm<1>, cudaFuncAttributeMaxDynamicSharedMemorySize, NODE_SMEM_BYTES);
    cudaFuncSetAttribute(node_gemm<2>, cudaFuncAttributeMaxDynamicSharedMemorySize, NODE_SMEM_BYTES);
    cudaFuncSetAttribute(node_gemm<3>, cudaFuncAttributeMaxDynamicSharedMemorySize, NODE_SMEM_BYTES);
    cudaFuncSetAttribute(edge_kernel,  cudaFuncAttributeMaxDynamicSharedMemorySize, ESM_BYTES);

    k_init<<<1, 256>>>(st);
    k_count<<<(NN + 255) / 256, 256>>>(batch);

    for (int i = 0; i < 2; i++) {
        const float* hin = (i == 0) ? h : (const float*)0;  // null => g_hbuf
        node_gemm<0><<<NB_NODE, NTHREADS, NODE_SMEM_BYTES>>>(
            hin, lin1w + i * 128 * 130, lin1b + i * 128, batch, (float*)0, 0);
        node_gemm<1><<<NB_NODE, NTHREADS, NODE_SMEM_BYTES>>>(
            (const float*)0, cl1 + i * 128 * 128, (const float*)0, batch, (float*)0, 0);
        edge_kernel<<<EDGE_BLOCKS, ETHREADS, ESM_BYTES>>>(
            ea, ew, eidx, mw1 + i * 128 * 50, mb1 + i * 128,
            mw2 + i * 128 * 128, mb2 + i * 128);
        node_gemm<2><<<NB_NODE, NTHREADS, NODE_SMEM_BYTES>>>(
            (const float*)0, cl2 + i * 128 * 128, cl2b + i * 128, batch, (float*)0,
            (i == 0) ? 1 : 0);
        if (i == 0) k_state<<<1, 256>>>();
    }
    node_gemm<3><<<NB_NODE, NTHREADS, NODE_SMEM_BYTES>>>(
        (const float*)0, outw, outb, batch, out, 0);
}

// round 14
// speedup vs baseline: 1.7469x; 1.1583x over previous
#include <cuda_runtime.h>
#include <cuda_fp16.h>
#include <math.h>

#define NN 50000
#define EE 800000
#define HH 128
#define GG 50
#define FF 128
#define BB 256

#define TILE 128
#define PAD 132
#define NTHREADS 512
#define NB_NODE ((NN + TILE - 1) / TILE)   // 391
#define EDGE_BLOCKS 148
#define ETHREADS 384                       // 8 mma warps + 4 epilogue warps
#define NT2 (EE / 64)                      // 12500 64-edge tiles

typedef unsigned long long u64;
typedef unsigned u32;

// ---------------- scratch -------------------------------------------------------
__device__ __align__(16) float g_h2[NN * HH];
__device__ __align__(16) float g_xf[NN * FF];
__device__ __align__(16) float g_agg[NN * FF];
__device__ __align__(16) float g_hbuf[NN * HH];
__device__ float g_state2[BB * 2];
__device__ float g_pool[BB];
__device__ float g_cnt[BB];

__device__ __forceinline__ float ssp(float x) {
    float sp = (x > 15.0f) ? x : log1pf(__expf(x));
    return sp - 0.69314718055994531f;
}

// ---- packed fp32x2 helpers (node GEMMs) ---------------------------------------
__device__ __forceinline__ u64 pk2(float v) {
    u64 r;
    unsigned u = __float_as_uint(v);
    asm("mov.b64 %0, {%1, %1};" : "=l"(r) : "r"(u));
    return r;
}
__device__ __forceinline__ float2 upk(u64 p) {
    unsigned lo, hi;
    asm("mov.b64 {%0, %1}, %2;" : "=r"(lo), "=r"(hi) : "l"(p));
    return make_float2(__uint_as_float(lo), __uint_as_float(hi));
}
#define FMA2(acc, a, b) \
    asm("fma.rn.f32x2 %0, %1, %2, %0;" : "+l"(acc) : "l"(a), "l"(b))

template <int K, int LD>
__device__ __forceinline__ void gemm_tile_p(const float* __restrict__ sW,
                                            const float* __restrict__ sX,
                                            int f0, int t0, u64 acc[16]) {
    const float* xp = sX + t0;
    const float* wp = sW + f0;
#pragma unroll 4
    for (int k = 0; k < K; k++) {
        float4 w4 = *(const float4*)wp;
        ulonglong2 A0 = *(const ulonglong2*)xp;
        ulonglong2 A1 = *(const ulonglong2*)(xp + 4);
        u64 wd0 = pk2(w4.x), wd1 = pk2(w4.y), wd2 = pk2(w4.z), wd3 = pk2(w4.w);
        FMA2(acc[0],  A0.x, wd0); FMA2(acc[1],  A0.x, wd1);
        FMA2(acc[2],  A0.x, wd2); FMA2(acc[3],  A0.x, wd3);
        FMA2(acc[4],  A0.y, wd0); FMA2(acc[5],  A0.y, wd1);
        FMA2(acc[6],  A0.y, wd2); FMA2(acc[7],  A0.y, wd3);
        FMA2(acc[8],  A1.x, wd0); FMA2(acc[9],  A1.x, wd1);
        FMA2(acc[10], A1.x, wd2); FMA2(acc[11], A1.x, wd3);
        FMA2(acc[12], A1.y, wd0); FMA2(acc[13], A1.y, wd1);
        FMA2(acc[14], A1.y, wd2); FMA2(acc[15], A1.y, wd3);
        xp += LD;
        wp += 128;
    }
}

// ---- fp16 mma helpers ----------------------------------------------------------
__device__ __forceinline__ u32 packh2(float x, float y) {
    __half2 h = __floats2half2_rn(x, y);
    return *(u32*)&h;
}
#define MMA_F16(c, a, b) \
    asm volatile("mma.sync.aligned.m16n8k16.row.col.f32.f16.f16.f32 " \
        "{%0,%1,%2,%3}, {%4,%5,%6,%7}, {%8,%9}, {%0,%1,%2,%3};" \
        : "+f"((c)[0]), "+f"((c)[1]), "+f"((c)[2]), "+f"((c)[3]) \
        : "r"((a)[0]), "r"((a)[1]), "r"((a)[2]), "r"((a)[3]), \
          "r"((b)[0]), "r"((b)[1]))
#define BARX(id, n) asm volatile("bar.sync %0, %1;" :: "n"(id), "n"(n) : "memory")

// ---------------- small helper kernels -----------------------------------------
__global__ void k_init(const float* __restrict__ state_attr) {
    int b = blockIdx.x * blockDim.x + threadIdx.x;
    if (b < BB) {
        g_cnt[b] = 0.0f;
        g_pool[b] = 0.0f;
        g_state2[2 * b]     = state_attr[2 * b];
        g_state2[2 * b + 1] = state_attr[2 * b + 1];
    }
}
__global__ void k_count(const int* __restrict__ batch) {
    int n = blockIdx.x * blockDim.x + threadIdx.x;
    if (n < NN) atomicAdd(&g_cnt[batch[n]], 1.0f);
}
__global__ void k_state() {
    int b = threadIdx.x;
    if (b < BB) {
        float s = g_pool[b] / fmaxf(g_cnt[b], 1.0f);
        g_state2[2 * b]     = s;
        g_state2[2 * b + 1] = s;
        g_pool[b] = 0.0f;
    }
}

// ---------------- node GEMM kernel (unchanged champion config) -----------------
#define NODE_SMEM_FLOATS (17152 + TILE * PAD)
#define NODE_SMEM_BYTES  (NODE_SMEM_FLOATS * 4)

template <int MODE>
__global__ void __launch_bounds__(NTHREADS, 1)
node_gemm(const float* __restrict__ Xext, const float* __restrict__ W,
          const float* __restrict__ bias, const int* __restrict__ batch,
          float* __restrict__ Yext, int do_pool) {
    extern __shared__ float sm[];
    float* sW    = sm;
    float* sb    = sm + 16384;
    float* sw0   = sm + 16512;
    float* sw1   = sm + 16640;
    float* spool = sm + 16768;
    float* ssa0  = sm + 16896;
    float* ssa1  = sm + 17024;
    float* sX    = sm + 17152;

    const int tid = threadIdx.x;
    const int n0  = blockIdx.x * TILE;

    const float* X;
    float* Y;
    float* aux = 0;
    if (MODE == 0)      { X = Xext ? Xext : g_hbuf; Y = g_h2;   aux = g_agg; }
    else if (MODE == 1) { X = g_h2;                 Y = g_xf; }
    else if (MODE == 2) { X = g_agg;                Y = g_hbuf; aux = g_h2; }
    else                { X = g_hbuf;               Y = Yext; }

    constexpr int ldw  = (MODE == 0) ? 130 : 128;
    constexpr int woff = (MODE == 0) ? 2 : 0;

    for (int i = tid; i < 128 * 128; i += NTHREADS) {
        int f = i >> 7, k = i & 127;
        sW[k * 128 + f] = W[f * ldw + woff + k];
    }
    if (tid < 128) {
        sb[tid] = bias ? bias[tid] : 0.0f;
        spool[tid] = 0.0f;
        if (MODE == 0) {
            sw0[tid] = W[tid * 130];
            sw1[tid] = W[tid * 130 + 1];
            float a0 = 0.0f, a1 = 0.0f;
            int n = n0 + tid;
            if (n < NN) {
                int b = batch[n];
                a0 = g_state2[2 * b];
                a1 = g_state2[2 * b + 1];
            }
            ssa0[tid] = a0;
            ssa1[tid] = a1;
        }
    }
    for (int i = tid; i < TILE * 128; i += NTHREADS) {
        int t = i >> 7, k = i & 127;
        int n = n0 + t;
        sX[k * PAD + t] = (n < NN) ? X[(size_t)n * 128 + k] : 0.0f;
    }
    __syncthreads();

    const int f0 = (tid & 31) * 4;
    const int t0 = (tid >> 5) * 8;

    u64 acc[16];
    if (MODE == 1) {
#pragma unroll
        for (int i = 0; i < 16; i++) acc[i] = 0ull;
    } else {
#pragma unroll
        for (int fi = 0; fi < 4; fi++) {
            u64 bp = pk2(sb[f0 + fi]);
            acc[0 * 4 + fi] = bp;
            acc[1 * 4 + fi] = bp;
            acc[2 * 4 + fi] = bp;
            acc[3 * 4 + fi] = bp;
        }
    }

    if (MODE == 0) {
        ulonglong2 Sa = *(const ulonglong2*)&ssa0[t0];
        ulonglong2 Sb = *(const ulonglong2*)&ssa0[t0 + 4];
        ulonglong2 Ta = *(const ulonglong2*)&ssa1[t0];
        ulonglong2 Tb = *(const ulonglong2*)&ssa1[t0 + 4];
#pragma unroll
        for (int fi = 0; fi < 4; fi++) {
            u64 w0d = pk2(sw0[f0 + fi]);
            u64 w1d = pk2(sw1[f0 + fi]);
            FMA2(acc[0 * 4 + fi], Sa.x, w0d);
            FMA2(acc[1 * 4 + fi], Sa.y, w0d);
            FMA2(acc[2 * 4 + fi], Sb.x, w0d);
            FMA2(acc[3 * 4 + fi], Sb.y, w0d);
            FMA2(acc[0 * 4 + fi], Ta.x, w1d);
            FMA2(acc[1 * 4 + fi], Ta.y, w1d);
            FMA2(acc[2 * 4 + fi], Tb.x, w1d);
            FMA2(acc[3 * 4 + fi], Tb.y, w1d);
        }
    }

    gemm_tile_p<128, PAD>(sW, sX, f0, t0, acc);

#pragma unroll
    for (int tp = 0; tp < 4; tp++) {
        float2 p0 = upk(acc[tp * 4 + 0]);
        float2 p1 = upk(acc[tp * 4 + 1]);
        float2 p2 = upk(acc[tp * 4 + 2]);
        float2 p3 = upk(acc[tp * 4 + 3]);
        float4 v[2];
        v[0] = make_float4(p0.x, p1.x, p2.x, p3.x);
        v[1] = make_float4(p0.y, p1.y, p2.y, p3.y);
#pragma unroll
        for (int hh = 0; hh < 2; hh++) {
            int t = t0 + 2 * tp + hh;
            int n = n0 + t;
            if (n >= NN) continue;
            size_t off = (size_t)n * 128 + f0;
            if (MODE == 0) {
                *(float4*)&Y[off]   = v[hh];
                *(float4*)&aux[off] = make_float4(0.f, 0.f, 0.f, 0.f);
            } else if (MODE == 2) {
                float4 h2v = *(const float4*)&aux[off];
                float4 o;
                o.x = h2v.x + ssp(v[hh].x);
                o.y = h2v.y + ssp(v[hh].y);
                o.z = h2v.z + ssp(v[hh].z);
                o.w = h2v.w + ssp(v[hh].w);
                *(float4*)&Y[off] = o;
                if (do_pool) atomicAdd(&spool[t], o.x + o.y + o.z + o.w);
            } else {
                *(float4*)&Y[off] = v[hh];
            }
        }
    }

    if (MODE == 2 && do_pool) {
        __syncthreads();
        if (tid < TILE) {
            int n = n0 + tid;
            if (n < NN) atomicAdd(&g_pool[batch[n]], spool[tid]);
        }
    }
}

// ---------------- edge kernel: fp16 m16n8k16 warp-specialized pipeline ---------
// u32 offsets in smem
#define SW1P  0        // 4096  W1 b-frags (kc4 x nbg16 x lane32 x 2)
#define SW2P  4096     // 8192  W2 b-frags (kc8 ...)
#define SZB   12288    // 4352  z tile: 64 rows x 68 u32 (half2)
#define SOUT0 16640    // 8448  out buffer 0 (fp32, 64x132)
#define SOUT1 25088    // 8448  out buffer 1
#define SF0   33536    // 2496  FILL buffer 0
#define SF1   36032    // 2496  FILL buffer 1
#define SB1V  38528    // 128 f32
#define SB2V  38656    // 128 f32
#define ESM_U32 38784
#define ESM_BYTES (ESM_U32 * 4)   // 155136 B
// FILL sublayout (u32)
#define FEA  0        // 64 rows x 36 u32 (halves [e][k], k 0..63)
#define FC   2304     // 64 f32
#define FSRC 2368     // 64 int
#define FDST 2432     // 64 int

__device__ __forceinline__ void edge_fill(u32* __restrict__ F, int e0, int et,
                                          const float* __restrict__ ea,
                                          const float* __restrict__ ew,
                                          const int* __restrict__ eidx) {
    for (int i = et; i < 64 * 32; i += 128) {
        int e = i >> 5, j = i & 31;
        float2 v = make_float2(0.0f, 0.0f);
        if (j < 25) v = *(const float2*)(ea + (size_t)(e0 + e) * GG + 2 * j);
        F[FEA + e * 36 + j] = packh2(v.x, v.y);
    }
    if (et < 64) {
        int e = e0 + et;
        ((float*)F)[FC + et] = 0.5f * (__cosf(ew[e] * 0.62831853071795864769f) + 1.0f);
        ((int*)F)[FSRC + et] = eidx[e];
        ((int*)F)[FDST + et] = eidx[EE + e];
    }
}

__device__ __forceinline__ void edge_scatter(const float* __restrict__ OUTb,
                                             const u32* __restrict__ Fm, int et) {
    int e  = et >> 1;
    int fh = (et & 1) * 64;
    float c = ((const float*)Fm)[FC + e];
    int s = ((const int*)Fm)[FSRC + e];
    int d = ((const int*)Fm)[FDST + e];
    const float* orow = OUTb + e * 132 + fh;
    const float* xb = g_xf + (size_t)s * 128 + fh;
    float* ab = g_agg + (size_t)d * 128 + fh;
#pragma unroll
    for (int q = 0; q < 16; q++) {
        float4 v = *(const float4*)(orow + 4 * q);
        float4 x = *(const float4*)(xb + 4 * q);
        float mx = v.x * c * x.x;
        float my = v.y * c * x.y;
        float mz = v.z * c * x.z;
        float mw = v.w * c * x.w;
        asm volatile("red.global.add.v4.f32 [%0], {%1, %2, %3, %4};"
                     :: "l"(ab + 4 * q), "f"(mx), "f"(my), "f"(mz), "f"(mw)
                     : "memory");
    }
}

__global__ void __launch_bounds__(ETHREADS, 1)
edge_kernel(const float* __restrict__ ea, const float* __restrict__ ew,
            const int* __restrict__ eidx,
            const float* __restrict__ W1, const float* __restrict__ b1,
            const float* __restrict__ W2, const float* __restrict__ b2) {
    extern __shared__ float smf[];
    u32* sm = (u32*)smf;
    const int tid  = threadIdx.x;
    const int wid  = tid >> 5;
    const int lane = tid & 31;

    // pack W1 b-frags: kc(4) x nbg(16) x lane(32), K padded 50->64
    for (int e = tid; e < 4 * 16 * 32; e += ETHREADS) {
        int kc = e >> 9, rem = e & 511;
        int nbg = rem >> 5, ln = rem & 31;
        int g = ln >> 2, tig = ln & 3;
        int f = nbg * 8 + g;
        int k0 = kc * 16 + 2 * tig;
        float v0 = (k0     < GG) ? W1[f * GG + k0]     : 0.0f;
        float v1 = (k0 + 1 < GG) ? W1[f * GG + k0 + 1] : 0.0f;
        float v8 = (k0 + 8 < GG) ? W1[f * GG + k0 + 8] : 0.0f;
        float v9 = (k0 + 9 < GG) ? W1[f * GG + k0 + 9] : 0.0f;
        sm[SW1P + e * 2]     = packh2(v0, v1);
        sm[SW1P + e * 2 + 1] = packh2(v8, v9);
    }
    // pack W2 b-frags: kc(8) x nbg(16) x lane(32)
    for (int e = tid; e < 8 * 16 * 32; e += ETHREADS) {
        int kc = e >> 9, rem = e & 511;
        int nbg = rem >> 5, ln = rem & 31;
        int g = ln >> 2, tig = ln & 3;
        int f = nbg * 8 + g;
        int k0 = kc * 16 + 2 * tig;
        sm[SW2P + e * 2]     = packh2(W2[f * 128 + k0],     W2[f * 128 + k0 + 1]);
        sm[SW2P + e * 2 + 1] = packh2(W2[f * 128 + k0 + 8], W2[f * 128 + k0 + 9]);
    }
    if (tid < 128) {
        ((float*)sm)[SB1V + tid] = b1[tid];
        ((float*)sm)[SB2V + tid] = b2[tid];
    }
    __syncthreads();

    const bool is_mma = (wid < 8);
    int it = 0;

    if (!is_mma)
        edge_fill(sm + SF0, blockIdx.x * 64, tid - 256, ea, ew, eidx);
    BARX(3, 384);

    for (int t = blockIdx.x; t < NT2; t += EDGE_BLOCKS, it++) {
        u32* F      = sm + ((it & 1) ? SF1 : SF0);
        float* OUTc = (float*)sm + ((it & 1) ? SOUT1 : SOUT0);
        if (is_mma) {
            const int g = lane >> 2, tig = lane & 3;
            const int mq = wid >> 1, nh = wid & 1;
            const int r0 = mq * 16;
            const float* sb1v = (const float*)sm + SB1V;
            const float* sb2v = (const float*)sm + SB2V;
            float acc[8][4];
#pragma unroll
            for (int nb = 0; nb < 8; nb++)
#pragma unroll
                for (int q = 0; q < 4; q++) acc[nb][q] = 0.0f;

            // stage 1: K=64 (4 chunks of 16)
#pragma unroll
            for (int kc = 0; kc < 4; kc++) {
                u32 a[4];
                const u32* p = F + FEA + (r0 + g) * 36 + kc * 8 + tig;
                a[0] = p[0];
                a[1] = p[8 * 36];
                a[2] = p[4];
                a[3] = p[8 * 36 + 4];
#pragma unroll
                for (int nb = 0; nb < 8; nb++) {
                    uint2 bb = *(const uint2*)&sm[SW1P + ((kc * 16 + nh * 8 + nb) * 32 + lane) * 2];
                    u32 b[2] = {bb.x, bb.y};
                    MMA_F16(acc[nb], a, b);
                }
            }
            // z = half2(ssp(acc + b1)) -> SZB [e][f/2], stride 68
#pragma unroll
            for (int nb = 0; nb < 8; nb++) {
                int col = nh * 64 + nb * 8 + 2 * tig;
                float bv0 = sb1v[col], bv1 = sb1v[col + 1];
                int c2 = nh * 32 + nb * 4 + tig;
                sm[SZB + (r0 + g) * 68 + c2]     = packh2(ssp(acc[nb][0] + bv0), ssp(acc[nb][1] + bv1));
                sm[SZB + (r0 + g + 8) * 68 + c2] = packh2(ssp(acc[nb][2] + bv0), ssp(acc[nb][3] + bv1));
            }
            BARX(1, 256);

            // stage 2: K=128 (8 chunks of 16)
#pragma unroll
            for (int nb = 0; nb < 8; nb++)
#pragma unroll
                for (int q = 0; q < 4; q++) acc[nb][q] = 0.0f;
#pragma unroll
            for (int kc = 0; kc < 8; kc++) {
                u32 a[4];
                const u32* p = sm + SZB + (r0 + g) * 68 + kc * 8 + tig;
                a[0] = p[0];
                a[1] = p[8 * 68];
                a[2] = p[4];
                a[3] = p[8 * 68 + 4];
#pragma unroll
                for (int nb = 0; nb < 8; nb++) {
                    uint2 bb = *(const uint2*)&sm[SW2P + ((kc * 16 + nh * 8 + nb) * 32 + lane) * 2];
                    u32 b[2] = {bb.x, bb.y};
                    MMA_F16(acc[nb], a, b);
                }
            }
            // OUT(t) = acc + b2 (fp32)
#pragma unroll
            for (int nb = 0; nb < 8; nb++) {
                int col = nh * 64 + nb * 8 + 2 * tig;
                float bv0 = sb2v[col], bv1 = sb2v[col + 1];
                float2 lo, hi;
                lo.x = acc[nb][0] + bv0;
                lo.y = acc[nb][1] + bv1;
                hi.x = acc[nb][2] + bv0;
                hi.y = acc[nb][3] + bv1;
                *(float2*)&OUTc[(r0 + g) * 132 + col]     = lo;
                *(float2*)&OUTc[(r0 + g + 8) * 132 + col] = hi;
            }
        } else {
            int et = tid - 256;
            if (it > 0) {
                u32* Fp     = sm + ((it & 1) ? SF0 : SF1);
                float* OUTp = (float*)sm + ((it & 1) ? SOUT0 : SOUT1);
                edge_scatter(OUTp, Fp, et);     // scatter tile t-1
            }
            BARX(4, 128);                       // meta read done before refill
            int tn = t + EDGE_BLOCKS;
            if (tn < NT2)
                edge_fill(sm + ((it & 1) ? SF0 : SF1), tn * 64, et, ea, ew, eidx);
        }
        BARX(3, 384);   // OUT(t) ready; FILL(t+1) ready; scatter(t-1) done
    }

    if (!is_mma && it > 0) {
        u32* Fl     = sm + (((it - 1) & 1) ? SF1 : SF0);
        float* OUTl = (float*)sm + (((it - 1) & 1) ? SOUT1 : SOUT0);
        edge_scatter(OUTl, Fl, tid - 256);
    }
}

// ---------------- launcher -----------------------------------------------------
extern "C" void kernel_launch(void* const* d_in, const int* in_sizes, int n_in,
                              void* d_out, int out_size) {
    const float* h      = (const float*)d_in[0];
    const float* ew     = (const float*)d_in[1];
    const float* ea     = (const float*)d_in[2];
    const float* st     = (const float*)d_in[3];
    const float* lin1w  = (const float*)d_in[4];
    const float* lin1b  = (const float*)d_in[5];
    const float* mw1    = (const float*)d_in[6];
    const float* mb1    = (const float*)d_in[7];
    const float* mw2    = (const float*)d_in[8];
    const float* mb2    = (const float*)d_in[9];
    const float* cl1    = (const float*)d_in[10];
    const float* cl2    = (const float*)d_in[11];
    const float* cl2b   = (const float*)d_in[12];
    const float* outw   = (const float*)d_in[13];
    const float* outb   = (const float*)d_in[14];
    const int* eidx  = (const int*)d_in[15];
    const int* batch = (const int*)d_in[16];
    float* out = (float*)d_out;

    cudaFuncSetAttribute(node_gemm<0>, cudaFuncAttributeMaxDynamicSharedMemorySize, NODE_SMEM_BYTES);
    cudaFuncSetAttribute(node_gemm<1>, cudaFuncAttributeMaxDynamicSharedMemorySize, NODE_SMEM_BYTES);
    cudaFuncSetAttribute(node_gemm<2>, cudaFuncAttributeMaxDynamicSharedMemorySize, NODE_SMEM_BYTES);
    cudaFuncSetAttribute(node_gemm<3>, cudaFuncAttributeMaxDynamicSharedMemorySize, NODE_SMEM_BYTES);
    cudaFuncSetAttribute(edge_kernel,  cudaFuncAttributeMaxDynamicSharedMemorySize, ESM_BYTES);

    k_init<<<1, 256>>>(st);
    k_count<<<(NN + 255) / 256, 256>>>(batch);

    for (int i = 0; i < 2; i++) {
        const float* hin = (i == 0) ? h : (const float*)0;  // null => g_hbuf
        node_gemm<0><<<NB_NODE, NTHREADS, NODE_SMEM_BYTES>>>(
            hin, lin1w + i * 128 * 130, lin1b + i * 128, batch, (float*)0, 0);
        node_gemm<1><<<NB_NODE, NTHREADS, NODE_SMEM_BYTES>>>(
            (const float*)0, cl1 + i * 128 * 128, (const float*)0, batch, (float*)0, 0);
        edge_kernel<<<EDGE_BLOCKS, ETHREADS, ESM_BYTES>>>(
            ea, ew, eidx, mw1 + i * 128 * 50, mb1 + i * 128,
            mw2 + i * 128 * 128, mb2 + i * 128);
        node_gemm<2><<<NB_NODE, NTHREADS, NODE_SMEM_BYTES>>>(
            (const float*)0, cl2 + i * 128 * 128, cl2b + i * 128, batch, (float*)0,
            (i == 0) ? 1 : 0);
        if (i == 0) k_state<<<1, 256>>>();
    }
    node_gemm<3><<<NB_NODE, NTHREADS, NODE_SMEM_BYTES>>>(
        (const float*)0, outw, outb, batch, out, 0);
}

// round 17
// speedup vs baseline: 2.0922x; 1.1976x over previous
#include <cuda_runtime.h>
#include <cuda_fp16.h>
#include <math.h>

#define NN 50000
#define EE 800000
#define HH 128
#define GG 50
#define FF 128
#define BB 256

#define TILE 128
#define NTHREADS 512
#define NB_NODE ((NN + TILE - 1) / TILE)   // 391
#define EDGE_BLOCKS 148
#define ETHREADS 384
#define NT2 (EE / 64)                      // 12500

typedef unsigned long long u64;
typedef unsigned u32;

// ---------------- scratch -------------------------------------------------------
__device__ __align__(16) float g_h2[NN * HH];
__device__ __align__(16) float g_xf[NN * FF];
__device__ __align__(16) float g_agg[NN * FF];
__device__ __align__(16) float g_hbuf[NN * HH];
__device__ float g_state2[BB * 2];
__device__ float g_pool[BB];
__device__ float g_cnt[BB];

__device__ __forceinline__ float ssp(float x) {
    float sp = (x > 15.0f) ? x : log1pf(__expf(x));
    return sp - 0.69314718055994531f;
}

__device__ __forceinline__ u32 packh2(float x, float y) {
    __half2 h = __floats2half2_rn(x, y);
    return *(u32*)&h;
}
#define MMA_F16(c, a, b) \
    asm volatile("mma.sync.aligned.m16n8k16.row.col.f32.f16.f16.f32 " \
        "{%0,%1,%2,%3}, {%4,%5,%6,%7}, {%8,%9}, {%0,%1,%2,%3};" \
        : "+f"((c)[0]), "+f"((c)[1]), "+f"((c)[2]), "+f"((c)[3]) \
        : "r"((a)[0]), "r"((a)[1]), "r"((a)[2]), "r"((a)[3]), \
          "r"((b)[0]), "r"((b)[1]))
#define BARX(id, n) asm volatile("bar.sync %0, %1;" :: "n"(id), "n"(n) : "memory")

// ---------------- small helper kernels -----------------------------------------
__global__ void k_init(const float* __restrict__ state_attr) {
    int b = blockIdx.x * blockDim.x + threadIdx.x;
    if (b < BB) {
        g_cnt[b] = 0.0f;
        g_pool[b] = 0.0f;
        g_state2[2 * b]     = state_attr[2 * b];
        g_state2[2 * b + 1] = state_attr[2 * b + 1];
    }
}
__global__ void k_count(const int* __restrict__ batch) {
    int n = blockIdx.x * blockDim.x + threadIdx.x;
    if (n < NN) atomicAdd(&g_cnt[batch[n]], 1.0f);
}
__global__ void k_state() {
    int b = threadIdx.x;
    if (b < BB) {
        float s = g_pool[b] / fmaxf(g_cnt[b], 1.0f);
        g_state2[2 * b]     = s;
        g_state2[2 * b + 1] = s;
        g_pool[b] = 0.0f;
    }
}

// ---------------- node GEMM kernel: fp16 m16n8k16 -------------------------------
// MODE 0: h2 = [sa,h] @ lin1_w^T + b  (+ fp32 rank-2 state correction), zero agg
// MODE 1: xf = g_h2 @ conv_lin1_w^T
// MODE 2: h  = g_h2 + ssp(g_agg @ conv_lin2_w^T + b)  (+pool)
// MODE 3: out = g_hbuf @ out_w^T + b
// smem (u32 offsets): sX 128x68=8704 | sW 8x16x32x2=8192 | then f32: sb sw0 sw1 ssa0 ssa1 spool
#define NSX   0
#define NSW   8704
#define NSB   16896
#define NSM_U32 (16896 + 768)
#define NSM_BYTES (NSM_U32 * 4)   // 70656 B

template <int MODE>
__global__ void __launch_bounds__(NTHREADS)
node_gemm(const float* __restrict__ Xext, const float* __restrict__ W,
          const float* __restrict__ bias, const int* __restrict__ batch,
          float* __restrict__ Yext, int do_pool) {
    extern __shared__ u32 sm[];
    u32* sX = sm + NSX;
    u32* sW = sm + NSW;
    float* sb    = (float*)(sm + NSB);
    float* sw0   = sb + 128;
    float* sw1   = sb + 256;
    float* ssa0  = sb + 384;
    float* ssa1  = sb + 512;
    float* spool = sb + 640;

    const int tid = threadIdx.x;
    const int n0  = blockIdx.x * TILE;

    const float* X;
    float* Y;
    float* aux = 0;
    if (MODE == 0)      { X = Xext ? Xext : g_hbuf; Y = g_h2;   aux = g_agg; }
    else if (MODE == 1) { X = g_h2;                 Y = g_xf; }
    else if (MODE == 2) { X = g_agg;                Y = g_hbuf; aux = g_h2; }
    else                { X = g_hbuf;               Y = Yext; }

    constexpr int ldw  = (MODE == 0) ? 130 : 128;
    constexpr int woff = (MODE == 0) ? 2 : 0;

    // pack W b-frags: kc(8) x nbg(16) x lane(32) x 2 u32
    for (int e = tid; e < 8 * 16 * 32; e += NTHREADS) {
        int kc = e >> 9, rem = e & 511;
        int nbg = rem >> 5, ln = rem & 31;
        int g = ln >> 2, tig = ln & 3;
        int f = nbg * 8 + g;
        int k0 = kc * 16 + 2 * tig;
        const float* wr = W + f * ldw + woff;
        sW[e * 2]     = packh2(wr[k0],     wr[k0 + 1]);
        sW[e * 2 + 1] = packh2(wr[k0 + 8], wr[k0 + 9]);
    }
    // pack X: [row][kpair] stride 68
    for (int i = tid; i < 128 * 64; i += NTHREADS) {
        int row = i >> 6, j = i & 63;
        int n = n0 + row;
        float2 v = (n < NN) ? *(const float2*)(X + (size_t)n * 128 + 2 * j)
                            : make_float2(0.0f, 0.0f);
        sX[row * 68 + j] = packh2(v.x, v.y);
    }
    if (tid < 128) {
        sb[tid] = bias ? bias[tid] : 0.0f;
        spool[tid] = 0.0f;
        if (MODE == 0) {
            sw0[tid] = W[tid * 130];
            sw1[tid] = W[tid * 130 + 1];
            float a0 = 0.0f, a1 = 0.0f;
            int n = n0 + tid;
            if (n < NN) {
                int b = batch[n];
                a0 = g_state2[2 * b];
                a1 = g_state2[2 * b + 1];
            }
            ssa0[tid] = a0;
            ssa1[tid] = a1;
        }
    }
    __syncthreads();

    const int wid  = tid >> 5;
    const int lane = tid & 31;
    const int g    = lane >> 2, tig = lane & 3;
    const int mq   = wid >> 1, nh = wid & 1;
    const int r0   = mq * 16;

    float acc[8][4];
#pragma unroll
    for (int nb = 0; nb < 8; nb++)
#pragma unroll
        for (int q = 0; q < 4; q++) acc[nb][q] = 0.0f;

#pragma unroll
    for (int kc = 0; kc < 8; kc++) {
        u32 a[4];
        const u32* p = sX + (r0 + g) * 68 + kc * 8 + tig;
        a[0] = p[0];
        a[1] = p[8 * 68];
        a[2] = p[4];
        a[3] = p[8 * 68 + 4];
#pragma unroll
        for (int nb = 0; nb < 8; nb++) {
            uint2 bb = *(const uint2*)&sW[((kc * 16 + nh * 8 + nb) * 32 + lane) * 2];
            u32 b[2] = {bb.x, bb.y};
            MMA_F16(acc[nb], a, b);
        }
    }

    const int rA = r0 + g;       // rows this thread owns
    const int rB = r0 + g + 8;
    const int nA = n0 + rA;
    const int nB = n0 + rB;

#pragma unroll
    for (int nb = 0; nb < 8; nb++) {
        int col = nh * 64 + nb * 8 + 2 * tig;
        float bv0 = sb[col], bv1 = sb[col + 1];
        float2 vA, vB;
        vA.x = acc[nb][0] + bv0;
        vA.y = acc[nb][1] + bv1;
        vB.x = acc[nb][2] + bv0;
        vB.y = acc[nb][3] + bv1;
        if (MODE == 0) {
            float w00 = sw0[col], w01 = sw0[col + 1];
            float w10 = sw1[col], w11 = sw1[col + 1];
            vA.x += ssa0[rA] * w00 + ssa1[rA] * w10;
            vA.y += ssa0[rA] * w01 + ssa1[rA] * w11;
            vB.x += ssa0[rB] * w00 + ssa1[rB] * w10;
            vB.y += ssa0[rB] * w01 + ssa1[rB] * w11;
        }
        if (MODE == 2) {
            if (nA < NN) {
                float2 h2v = *(const float2*)(aux + (size_t)nA * 128 + col);
                float2 o;
                o.x = h2v.x + ssp(vA.x);
                o.y = h2v.y + ssp(vA.y);
                *(float2*)(Y + (size_t)nA * 128 + col) = o;
                if (do_pool) atomicAdd(&spool[rA], o.x + o.y);
            }
            if (nB < NN) {
                float2 h2v = *(const float2*)(aux + (size_t)nB * 128 + col);
                float2 o;
                o.x = h2v.x + ssp(vB.x);
                o.y = h2v.y + ssp(vB.y);
                *(float2*)(Y + (size_t)nB * 128 + col) = o;
                if (do_pool) atomicAdd(&spool[rB], o.x + o.y);
            }
        } else {
            if (nA < NN) {
                *(float2*)(Y + (size_t)nA * 128 + col) = vA;
                if (MODE == 0)
                    *(float2*)(aux + (size_t)nA * 128 + col) = make_float2(0.f, 0.f);
            }
            if (nB < NN) {
                *(float2*)(Y + (size_t)nB * 128 + col) = vB;
                if (MODE == 0)
                    *(float2*)(aux + (size_t)nB * 128 + col) = make_float2(0.f, 0.f);
            }
        }
    }

    if (MODE == 2 && do_pool) {
        __syncthreads();
        if (tid < TILE) {
            int n = n0 + tid;
            if (n < NN) atomicAdd(&g_pool[batch[n]], spool[tid]);
        }
    }
}

// ---------------- edge kernel: fp16 m16n8k16 warp-specialized pipeline ---------
// u32 offsets in smem
#define SW1P  0        // 4096  W1 b-frags (kc4 x nbg16 x lane32 x 2)
#define SW2P  4096     // 8192  W2 b-frags (kc8 ...)
#define SZB   12288    // 4352  z tile: 64 rows x 68 u32 (half2)
#define SOUT0 16640    // 8448  out buffer 0 (fp32, 64x132)
#define SOUT1 25088    // 8448  out buffer 1
#define SF0   33536    // 2496  FILL buffer 0
#define SF1   36032    // 2496  FILL buffer 1
#define SB1V  38528    // 128 f32
#define SB2V  38656    // 128 f32
#define ESM_U32 38784
#define ESM_BYTES (ESM_U32 * 4)   // 155136 B
// FILL sublayout (u32)
#define FEA  0        // 64 rows x 36 u32 (halves [e][k], k 0..63)
#define FC   2304     // 64 f32
#define FSRC 2368     // 64 int
#define FDST 2432     // 64 int

__device__ __forceinline__ void edge_fill(u32* __restrict__ F, int e0, int et,
                                          const float* __restrict__ ea,
                                          const float* __restrict__ ew,
                                          const int* __restrict__ eidx) {
    for (int i = et; i < 64 * 32; i += 128) {
        int e = i >> 5, j = i & 31;
        float2 v = make_float2(0.0f, 0.0f);
        if (j < 25) v = *(const float2*)(ea + (size_t)(e0 + e) * GG + 2 * j);
        F[FEA + e * 36 + j] = packh2(v.x, v.y);
    }
    if (et < 64) {
        int e = e0 + et;
        ((float*)F)[FC + et] = 0.5f * (__cosf(ew[e] * 0.62831853071795864769f) + 1.0f);
        ((int*)F)[FSRC + et] = eidx[e];
        ((int*)F)[FDST + et] = eidx[EE + e];
    }
}

__device__ __forceinline__ void edge_scatter(const float* __restrict__ OUTb,
                                             const u32* __restrict__ Fm, int et) {
    int e  = et >> 1;
    int fh = (et & 1) * 64;
    float c = ((const float*)Fm)[FC + e];
    int s = ((const int*)Fm)[FSRC + e];
    int d = ((const int*)Fm)[FDST + e];
    const float* orow = OUTb + e * 132 + fh;
    const float* xb = g_xf + (size_t)s * 128 + fh;
    float* ab = g_agg + (size_t)d * 128 + fh;
#pragma unroll
    for (int q = 0; q < 16; q++) {
        float4 v = *(const float4*)(orow + 4 * q);
        float4 x = *(const float4*)(xb + 4 * q);
        float mx = v.x * c * x.x;
        float my = v.y * c * x.y;
        float mz = v.z * c * x.z;
        float mw = v.w * c * x.w;
        asm volatile("red.global.add.v4.f32 [%0], {%1, %2, %3, %4};"
                     :: "l"(ab + 4 * q), "f"(mx), "f"(my), "f"(mz), "f"(mw)
                     : "memory");
    }
}

__global__ void __launch_bounds__(ETHREADS, 1)
edge_kernel(const float* __restrict__ ea, const float* __restrict__ ew,
            const int* __restrict__ eidx,
            const float* __restrict__ W1, const float* __restrict__ b1,
            const float* __restrict__ W2, const float* __restrict__ b2) {
    extern __shared__ float smf[];
    u32* sm = (u32*)smf;
    const int tid  = threadIdx.x;
    const int wid  = tid >> 5;
    const int lane = tid & 31;

    for (int e = tid; e < 4 * 16 * 32; e += ETHREADS) {
        int kc = e >> 9, rem = e & 511;
        int nbg = rem >> 5, ln = rem & 31;
        int g = ln >> 2, tig = ln & 3;
        int f = nbg * 8 + g;
        int k0 = kc * 16 + 2 * tig;
        float v0 = (k0     < GG) ? W1[f * GG + k0]     : 0.0f;
        float v1 = (k0 + 1 < GG) ? W1[f * GG + k0 + 1] : 0.0f;
        float v8 = (k0 + 8 < GG) ? W1[f * GG + k0 + 8] : 0.0f;
        float v9 = (k0 + 9 < GG) ? W1[f * GG + k0 + 9] : 0.0f;
        sm[SW1P + e * 2]     = packh2(v0, v1);
        sm[SW1P + e * 2 + 1] = packh2(v8, v9);
    }
    for (int e = tid; e < 8 * 16 * 32; e += ETHREADS) {
        int kc = e >> 9, rem = e & 511;
        int nbg = rem >> 5, ln = rem & 31;
        int g = ln >> 2, tig = ln & 3;
        int f = nbg * 8 + g;
        int k0 = kc * 16 + 2 * tig;
        sm[SW2P + e * 2]     = packh2(W2[f * 128 + k0],     W2[f * 128 + k0 + 1]);
        sm[SW2P + e * 2 + 1] = packh2(W2[f * 128 + k0 + 8], W2[f * 128 + k0 + 9]);
    }
    if (tid < 128) {
        ((float*)sm)[SB1V + tid] = b1[tid];
        ((float*)sm)[SB2V + tid] = b2[tid];
    }
    __syncthreads();

    const bool is_mma = (wid < 8);
    int it = 0;

    if (!is_mma)
        edge_fill(sm + SF0, blockIdx.x * 64, tid - 256, ea, ew, eidx);
    BARX(3, 384);

    for (int t = blockIdx.x; t < NT2; t += EDGE_BLOCKS, it++) {
        u32* F      = sm + ((it & 1) ? SF1 : SF0);
        float* OUTc = (float*)sm + ((it & 1) ? SOUT1 : SOUT0);
        if (is_mma) {
            const int g = lane >> 2, tig = lane & 3;
            const int mq = wid >> 1, nh = wid & 1;
            const int r0 = mq * 16;
            const float* sb1v = (const float*)sm + SB1V;
            const float* sb2v = (const float*)sm + SB2V;
            float acc[8][4];
#pragma unroll
            for (int nb = 0; nb < 8; nb++)
#pragma unroll
                for (int q = 0; q < 4; q++) acc[nb][q] = 0.0f;

            // stage 1: K=64 (4 chunks of 16)
#pragma unroll
            for (int kc = 0; kc < 4; kc++) {
                u32 a[4];
                const u32* p = F + FEA + (r0 + g) * 36 + kc * 8 + tig;
                a[0] = p[0];
                a[1] = p[8 * 36];
                a[2] = p[4];
                a[3] = p[8 * 36 + 4];
#pragma unroll
                for (int nb = 0; nb < 8; nb++) {
                    uint2 bb = *(const uint2*)&sm[SW1P + ((kc * 16 + nh * 8 + nb) * 32 + lane) * 2];
                    u32 b[2] = {bb.x, bb.y};
                    MMA_F16(acc[nb], a, b);
                }
            }
            // z = half2(ssp(acc + b1)) -> SZB, stride 68
#pragma unroll
            for (int nb = 0; nb < 8; nb++) {
                int col = nh * 64 + nb * 8 + 2 * tig;
                float bv0 = sb1v[col], bv1 = sb1v[col + 1];
                int c2 = nh * 32 + nb * 4 + tig;
                sm[SZB + (r0 + g) * 68 + c2]     = packh2(ssp(acc[nb][0] + bv0), ssp(acc[nb][1] + bv1));
                sm[SZB + (r0 + g + 8) * 68 + c2] = packh2(ssp(acc[nb][2] + bv0), ssp(acc[nb][3] + bv1));
            }
            BARX(1, 256);

            // stage 2: K=128 (8 chunks of 16)
#pragma unroll
            for (int nb = 0; nb < 8; nb++)
#pragma unroll
                for (int q = 0; q < 4; q++) acc[nb][q] = 0.0f;
#pragma unroll
            for (int kc = 0; kc < 8; kc++) {
                u32 a[4];
                const u32* p = sm + SZB + (r0 + g) * 68 + kc * 8 + tig;
                a[0] = p[0];
                a[1] = p[8 * 68];
                a[2] = p[4];
                a[3] = p[8 * 68 + 4];
#pragma unroll
                for (int nb = 0; nb < 8; nb++) {
                    uint2 bb = *(const uint2*)&sm[SW2P + ((kc * 16 + nh * 8 + nb) * 32 + lane) * 2];
                    u32 b[2] = {bb.x, bb.y};
                    MMA_F16(acc[nb], a, b);
                }
            }
            // OUT(t) = acc + b2 (fp32)
#pragma unroll
            for (int nb = 0; nb < 8; nb++) {
                int col = nh * 64 + nb * 8 + 2 * tig;
                float bv0 = sb2v[col], bv1 = sb2v[col + 1];
                float2 lo, hi;
                lo.x = acc[nb][0] + bv0;
                lo.y = acc[nb][1] + bv1;
                hi.x = acc[nb][2] + bv0;
                hi.y = acc[nb][3] + bv1;
                *(float2*)&OUTc[(r0 + g) * 132 + col]     = lo;
                *(float2*)&OUTc[(r0 + g + 8) * 132 + col] = hi;
            }
        } else {
            int et = tid - 256;
            if (it > 0) {
                u32* Fp     = sm + ((it & 1) ? SF0 : SF1);
                float* OUTp = (float*)sm + ((it & 1) ? SOUT0 : SOUT1);
                edge_scatter(OUTp, Fp, et);
            }
            BARX(4, 128);
            int tn = t + EDGE_BLOCKS;
            if (tn < NT2)
                edge_fill(sm + ((it & 1) ? SF0 : SF1), tn * 64, et, ea, ew, eidx);
        }
        BARX(3, 384);
    }

    if (!is_mma && it > 0) {
        u32* Fl     = sm + (((it - 1) & 1) ? SF1 : SF0);
        float* OUTl = (float*)sm + (((it - 1) & 1) ? SOUT1 : SOUT0);
        edge_scatter(OUTl, Fl, tid - 256);
    }
}

// ---------------- launcher -----------------------------------------------------
extern "C" void kernel_launch(void* const* d_in, const int* in_sizes, int n_in,
                              void* d_out, int out_size) {
    const float* h      = (const float*)d_in[0];
    const float* ew     = (const float*)d_in[1];
    const float* ea     = (const float*)d_in[2];
    const float* st     = (const float*)d_in[3];
    const float* lin1w  = (const float*)d_in[4];
    const float* lin1b  = (const float*)d_in[5];
    const float* mw1    = (const float*)d_in[6];
    const float* mb1    = (const float*)d_in[7];
    const float* mw2    = (const float*)d_in[8];
    const float* mb2    = (const float*)d_in[9];
    const float* cl1    = (const float*)d_in[10];
    const float* cl2    = (const float*)d_in[11];
    const float* cl2b   = (const float*)d_in[12];
    const float* outw   = (const float*)d_in[13];
    const float* outb   = (const float*)d_in[14];
    const int* eidx  = (const int*)d_in[15];
    const int* batch = (const int*)d_in[16];
    float* out = (float*)d_out;

    cudaFuncSetAttribute(node_gemm<0>, cudaFuncAttributeMaxDynamicSharedMemorySize, NSM_BYTES);
    cudaFuncSetAttribute(node_gemm<1>, cudaFuncAttributeMaxDynamicSharedMemorySize, NSM_BYTES);
    cudaFuncSetAttribute(node_gemm<2>, cudaFuncAttributeMaxDynamicSharedMemorySize, NSM_BYTES);
    cudaFuncSetAttribute(node_gemm<3>, cudaFuncAttributeMaxDynamicSharedMemorySize, NSM_BYTES);
    cudaFuncSetAttribute(edge_kernel,  cudaFuncAttributeMaxDynamicSharedMemorySize, ESM_BYTES);

    k_init<<<1, 256>>>(st);
    k_count<<<(NN + 255) / 256, 256>>>(batch);

    for (int i = 0; i < 2; i++) {
        const float* hin = (i == 0) ? h : (const float*)0;  // null => g_hbuf
        node_gemm<0><<<NB_NODE, NTHREADS, NSM_BYTES>>>(
            hin, lin1w + i * 128 * 130, lin1b + i * 128, batch, (float*)0, 0);
        node_gemm<1><<<NB_NODE, NTHREADS, NSM_BYTES>>>(
            (const float*)0, cl1 + i * 128 * 128, (const float*)0, batch, (float*)0, 0);
        edge_kernel<<<EDGE_BLOCKS, ETHREADS, ESM_BYTES>>>(
            ea, ew, eidx, mw1 + i * 128 * 50, mb1 + i * 128,
            mw2 + i * 128 * 128, mb2 + i * 128);
        node_gemm<2><<<NB_NODE, NTHREADS, NSM_BYTES>>>(
            (const float*)0, cl2 + i * 128 * 128, cl2b + i * 128, batch, (float*)0,
            (i == 0) ? 1 : 0);
        if (i == 0) k_state<<<1, 256>>>();
    }
    node_gemm<3><<<NB_NODE, NTHREADS, NSM_BYTES>>>(
        (const float*)0, outw, outb, batch, out, 0);
}